// round 14
// baseline (speedup 1.0000x reference)
#include <cuda_runtime.h>
#include <math.h>

#define FULLMASK 0xffffffffu

typedef unsigned long long u64;
typedef unsigned int u32;

#define PACK2(d, x, y)  asm("mov.b64 %0, {%1, %2};" : "=l"(d) : "f"(x), "f"(y))
#define UNPACK2(x, y, s) asm("mov.b64 {%0, %1}, %2;" : "=f"(x), "=f"(y) : "l"(s))
#define FMA2(d, a, b, c) asm("fma.rn.f32x2 %0, %1, %2, %3;" : "=l"(d) : "l"(a), "l"(b), "l"(c))

// Fixed problem sizes: B=2, N=64, D=256, R=128, K=16, H=256, ORD=3
constexpr int CB = 2, CN = 64, CK = 16;

// Dynamic smem layout (bytes), JB=16 edges per block
constexpr int SM_AF_BYTES  = 32896;                   // 8224 u32 (s_af / s_tw; post: hid16, eh16)
constexpr int SM_X_OFF     = SM_AF_BYTES;             // 640*16 floats = 40960 B
constexpr int SM_MIX_OFF   = SM_X_OFF + 40960;        // 512*16 floats = 32768 B (post: s_v16)
constexpr int SM_RED_OFF   = SM_MIX_OFF + 32768;      // 256 floats
constexpr int SM_LOGIT_OFF = SM_RED_OFF + 1024;       // 32 floats
constexpr int SM_CRH_OFF   = SM_LOGIT_OFF + 128;      // 48 floats
constexpr int SM_RH_OFF    = SM_CRH_OFF + 192;        // 48 floats
constexpr int SM_TK_OFF    = SM_RH_OFF + 192;         // 16 ints
constexpr int SM_TOTAL     = SM_TK_OFF + 64;          // 108288 B

// ---------------- device scratch ----------------
// Fragment-ordered GEMM weights: [kt:32][w:8][lane:32][half:2][nt:8] tf32 bits.
__device__ u32 g_Wmma[32 * 8 * 32 * 16];
__device__ float g_cvec[256];                  // tp_b2 @ ts_w1a + ts_b1 (fp32)
__device__ int   g_topk[CB * CN * CK];
__device__ float g_radpre[CB * CN * CK * 256]; // comp_rbf @ tp_w1[4:] + tp_b1
__device__ float g_nfpre[CB * CN * CK * 256];  // comp_feat @ ts_w1[256:]
__device__ float g_ef[CB * CN * CN * 256];
__device__ float g_bondp[CB * CN * 256];

__device__ __forceinline__ float siluf(float x) { return x * __frcp_rn(1.f + __expf(-x)); }
__device__ __forceinline__ float sigmf(float x) { return __frcp_rn(1.f + __expf(-x)); }
__device__ __forceinline__ u32 f2tf(float x) {
    u32 r; asm("cvt.rna.tf32.f32 %0, %1;" : "=r"(r) : "f"(x)); return r;
}

__device__ __forceinline__ void mma_tf32(float* d, const u32* a, u32 b0, u32 b1) {
    asm volatile(
        "mma.sync.aligned.m16n8k8.row.col.f32.tf32.tf32.f32 "
        "{%0,%1,%2,%3}, {%4,%5,%6,%7}, {%8,%9}, {%0,%1,%2,%3};"
        : "+f"(d[0]), "+f"(d[1]), "+f"(d[2]), "+f"(d[3])
        : "r"(a[0]), "r"(a[1]), "r"(a[2]), "r"(a[3]), "r"(b0), "r"(b1));
}

// Deterministic block-wide reduction of (sum, sumsq). scr >= 18 floats.
__device__ __forceinline__ float2 block_reduce2(float sx, float sy, float* scr) {
    #pragma unroll
    for (int off = 16; off; off >>= 1) {
        sx += __shfl_down_sync(FULLMASK, sx, off);
        sy += __shfl_down_sync(FULLMASK, sy, off);
    }
    int w = threadIdx.x >> 5;
    if ((threadIdx.x & 31) == 0) { scr[w] = sx; scr[8 + w] = sy; }
    __syncthreads();
    if (threadIdx.x == 0) {
        float ax = 0.f, ay = 0.f;
        #pragma unroll
        for (int q = 0; q < 8; q++) { ax += scr[q]; ay += scr[8 + q]; }
        scr[16] = ax; scr[17] = ay;
    }
    __syncthreads();
    float2 res = make_float2(scr[16], scr[17]);
    __syncthreads();
    return res;
}

// ------------- prep: fragment-ordered Wmma (tf32 bits), cvec -----------------
__global__ __launch_bounds__(256) void prep_wc_kernel(
    const float* __restrict__ tp_w2, const float* __restrict__ ts_w1,
    const float* __restrict__ tp_b2, const float* __restrict__ ts_b1) {
    __shared__ float row[256];
    int t = threadIdx.x;
    int d = blockIdx.x;
    if (d < 256) {
        float wv = tp_w2[d * 256 + t];
        row[t] = wv;
        __syncthreads();
        float acc = 0.f;
        #pragma unroll 4
        for (int e = 0; e < 256; e++) acc = fmaf(row[e], ts_w1[e * 256 + t], acc);
        int kt = d >> 3, r = d & 7, half = r >> 2, tg = r & 3;
        #pragma unroll
        for (int s = 0; s < 2; s++) {
            int n = 2 * t + s;
            int w = n >> 6, rem = n & 63, nt = rem >> 3, g = rem & 7;
            int lane = g * 4 + tg;
            g_Wmma[(((kt * 8 + w) * 32 + lane) << 4) + half * 8 + nt] =
                f2tf(s ? acc : wv);
        }
    } else {
        row[t] = tp_b2[t];
        __syncthreads();
        float acc = ts_b1[t];
        #pragma unroll 4
        for (int e = 0; e < 256; e++) acc = fmaf(row[e], ts_w1[e * 256 + t], acc);
        g_cvec[t] = acc;
    }
}

// ------------- top-16 smallest dist per (b,i); ties -> lower index ----------
__global__ void topk_kernel(const float* __restrict__ dist) {
    int blk = blockIdx.x;           // b*64 + i
    int lane = threadIdx.x;
    const float* dr = dist + (size_t)blk * 64;
    float v0 = dr[lane], v1 = dr[lane + 32];
    for (int k = 0; k < 16; k++) {
        float bv = v0; int bj = lane;
        if (v1 < bv) { bv = v1; bj = lane + 32; }
        #pragma unroll
        for (int off = 16; off; off >>= 1) {
            float ov = __shfl_down_sync(FULLMASK, bv, off);
            int   oj = __shfl_down_sync(FULLMASK, bj, off);
            if (ov < bv || (ov == bv && oj < bj)) { bv = ov; bj = oj; }
        }
        int sel = __shfl_sync(FULLMASK, bj, 0);
        if (lane == 0) g_topk[blk * 16 + k] = sel;
        if (sel == lane)      v0 = INFINITY;
        if (sel == lane + 32) v1 = INFINITY;
    }
}

// ------------- per-(b,i,k) precompute: rad_pre, nf_pre ----------------------
__global__ __launch_bounds__(256) void pre_kernel(
    const float* __restrict__ node_s, const float* __restrict__ rbf,
    const float* __restrict__ tp_w1, const float* __restrict__ tp_b1,
    const float* __restrict__ ts_w1) {
    __shared__ float s_rbf[128];
    __shared__ float s_nd[256];
    int r = blockIdx.x;   // (b*64+i)*16 + k
    int t = threadIdx.x;
    int bi = r >> 4;
    int b = bi >> 6;
    int jk = g_topk[r];
    if (t < 128) s_rbf[t] = rbf[((size_t)bi * 64 + jk) * 128 + t];
    s_nd[t] = node_s[((size_t)b * 64 + jk) * 256 + t];
    __syncthreads();
    float rad = tp_b1[t];
    #pragma unroll 4
    for (int e = 0; e < 128; e++) rad = fmaf(s_rbf[e], tp_w1[(4 + e) * 256 + t], rad);
    float nf = 0.f;
    #pragma unroll 4
    for (int e = 0; e < 256; e++) nf = fmaf(s_nd[e], ts_w1[(256 + e) * 256 + t], nf);
    g_radpre[(size_t)r * 256 + t] = rad;
    g_nfpre[(size_t)r * 256 + t]  = nf;
}

// ------------- main fused edge kernel: 16 edges (j0..j0+15) per block -------
__global__ __launch_bounds__(256, 2) void edge_kernel(
    const float* __restrict__ node_s, const float* __restrict__ rbf,
    const float* __restrict__ r_hat,
    const float* __restrict__ tp_w1, const float* __restrict__ tp_b2,
    const float* __restrict__ ts_w2, const float* __restrict__ ts_b2,
    const float* __restrict__ ep_w1, const float* __restrict__ ep_b1,
    const float* __restrict__ ep_w2, const float* __restrict__ ep_b2,
    const float* __restrict__ mix_ln_g, const float* __restrict__ mix_ln_b,
    const float* __restrict__ mix_w1, const float* __restrict__ mix_b1,
    const float* __restrict__ mix_w2, const float* __restrict__ mix_b2,
    const float* __restrict__ gate_w, const float* __restrict__ gate_b,
    const float* __restrict__ edge_ln_g, const float* __restrict__ edge_ln_b) {

    extern __shared__ __align__(16) char smem_raw[];
    u32*   s_af    = (u32*)smem_raw;                    // [8224] mma A fragments
    float* s_tw    = (float*)smem_raw;                  // alias: [32][257]
    float* s_hid16 = (float*)smem_raw;                  // alias post-loop: [256*16] (16 KB)
    float* s_eh16  = (float*)(smem_raw) + 4096;         // alias post-loop: [256*16] (16-32 KB)
    float* s_x16   = (float*)(smem_raw + SM_X_OFF);     // [640*16]
    float* s_mix16 = (float*)(smem_raw + SM_MIX_OFF);   // [512*16]
    float* s_v16   = s_mix16;                           // alias post-phase-5: [256*16]
    float* s_red   = (float*)(smem_raw + SM_RED_OFF);   // [256]
    float* s_logit = (float*)(smem_raw + SM_LOGIT_OFF); // [32]
    float* s_crh   = (float*)(smem_raw + SM_CRH_OFF);   // [16*3]
    float* s_rh    = (float*)(smem_raw + SM_RH_OFF);    // [16*3]
    int*   s_tk    = (int*)(smem_raw + SM_TK_OFF);      // [16]

    int t = threadIdx.x;
    int lane = t & 31;
    int w = t >> 5;       // warp 0..7
    int g = lane >> 2;    // groupID 0..7
    int tg = lane & 3;    // threadInGroup 0..3
    int bx = blockIdx.x;
    int b = bx >> 8;
    int rem = bx & 255;
    int i = rem >> 2;
    int j0 = (rem & 3) * 16;
    int bi = b * 64 + i;

    // ---- Phase 0: stage inputs for all 16 edges ----
    {
        float nsit = node_s[(size_t)bi * 256 + t];
        #pragma unroll
        for (int jj = 0; jj < 16; jj++) s_x16[t * 16 + jj] = nsit;
        #pragma unroll
        for (int jj = 0; jj < 16; jj++)
            s_x16[(256 + t) * 16 + jj] = node_s[((size_t)b * 64 + j0 + jj) * 256 + t];
        if (t < 128) {
            #pragma unroll
            for (int jj = 0; jj < 16; jj++)
                s_x16[(512 + t) * 16 + jj] = rbf[((size_t)bi * 64 + j0 + jj) * 128 + t];
        }
        if (t < 16) s_tk[t] = g_topk[bi * 16 + t];
        if (t < 48) s_crh[t] = r_hat[((size_t)bi * 64 + g_topk[bi * 16 + t / 3]) * 3 + (t % 3)];
        if (t < 48) s_rh[t] = r_hat[((size_t)bi * 64 + j0 + t / 3) * 3 + (t % 3)];
    }
    __syncthreads();

    // ==== jg loop: 8 passes x 2 edges through phases 1-4 ====
    for (int jg = 0; jg < 8; jg++) {
        // ---- Phase 1: a[row][e=t] = silu(layer1), scattered into fragment order
        {
            float w1_0 = tp_w1[t], w1_1 = tp_w1[256 + t], w1_2 = tp_w1[512 + t], w1_3 = tp_w1[768 + t];
            int ekt = t >> 3, etg = t & 3, ehi = (t >> 2) & 1;
            #pragma unroll
            for (int jj = 0; jj < 2; jj++) {
                int ej = 2 * jg + jj;
                float rx = s_rh[ej * 3], ry = s_rh[ej * 3 + 1], rz = s_rh[ej * 3 + 2];
                #pragma unroll
                for (int k = 0; k < 16; k++) {
                    float c = rx * s_crh[k * 3] + ry * s_crh[k * 3 + 1] + rz * s_crh[k * 3 + 2];
                    c = fminf(fmaxf(c, -1.f + 1e-6f), 1.f - 1e-6f);
                    float p1 = c;
                    float p2 = (3.f * c * p1 - 1.f) * 0.5f;
                    float p3 = (5.f * c * p2 - 2.f * p1) * (1.f / 3.f);
                    float h = g_radpre[((size_t)bi * 16 + k) * 256 + t] + w1_0;
                    h = fmaf(p1, w1_1, h);
                    h = fmaf(p2, w1_2, h);
                    h = fmaf(p3, w1_3, h);
                    int gw = k & 7;
                    int lw = gw * 4 + etg;
                    int q = ((k >> 3) & 1) + 2 * ehi;
                    s_af[ekt * 256 + lw * 8 + ((jj * 4) ^ (lw & 4)) + q] = f2tf(siluf(h));
                }
            }
        }
        __syncthreads();

        // ---- Phase 2: tensor-core GEMM C[32x512] = A[32x256] @ W[256x512] ----
        float acc[2][8][4];
        #pragma unroll
        for (int mt = 0; mt < 2; mt++)
            #pragma unroll
            for (int nt = 0; nt < 8; nt++)
                #pragma unroll
                for (int q = 0; q < 4; q++) acc[mt][nt][q] = 0.f;
        {
            int sw = lane & 4;
            const uint4* wbase = reinterpret_cast<const uint4*>(g_Wmma) + ((w * 32 + lane) << 2);
            #pragma unroll 2
            for (int kt = 0; kt < 32; kt++) {
                const uint4* wr = wbase + (kt << 10);
                uint4 B0 = wr[0];
                uint4 B1 = wr[1];
                uint4 B2 = wr[2];
                uint4 B3 = wr[3];
                const u32* ab = s_af + kt * 256 + lane * 8;
                uint4 A0 = *(const uint4*)(ab + sw);
                uint4 A1 = *(const uint4*)(ab + (4 ^ sw));
                u32 a0[4] = {A0.x, A0.y, A0.z, A0.w};
                u32 a1[4] = {A1.x, A1.y, A1.z, A1.w};
                mma_tf32(acc[0][0], a0, B0.x, B2.x);
                mma_tf32(acc[1][0], a1, B0.x, B2.x);
                mma_tf32(acc[0][1], a0, B0.y, B2.y);
                mma_tf32(acc[1][1], a1, B0.y, B2.y);
                mma_tf32(acc[0][2], a0, B0.z, B2.z);
                mma_tf32(acc[1][2], a1, B0.z, B2.z);
                mma_tf32(acc[0][3], a0, B0.w, B2.w);
                mma_tf32(acc[1][3], a1, B0.w, B2.w);
                mma_tf32(acc[0][4], a0, B1.x, B3.x);
                mma_tf32(acc[1][4], a1, B1.x, B3.x);
                mma_tf32(acc[0][5], a0, B1.y, B3.y);
                mma_tf32(acc[1][5], a1, B1.y, B3.y);
                mma_tf32(acc[0][6], a0, B1.z, B3.z);
                mma_tf32(acc[1][6], a1, B1.z, B3.z);
                mma_tf32(acc[0][7], a0, B1.w, B3.w);
                mma_tf32(acc[1][7], a1, B1.w, B3.w);
            }
        }

        // ---- Phase 3: logits from ts accumulators ----
        {
            float vs0 = 0.f, vs1 = 0.f, vs2 = 0.f, vs3 = 0.f;
            #pragma unroll
            for (int nt = 0; nt < 8; nt++) {
                int tt = w * 32 + nt * 4 + tg;
                float cv = g_cvec[tt];
                float w2 = ts_w2[tt];
                const float* nfb = g_nfpre + (size_t)bi * 4096 + tt;
                float h0 = acc[0][nt][1] + cv + nfb[g * 256];
                float h1 = acc[0][nt][3] + cv + nfb[(g + 8) * 256];
                float h2 = acc[1][nt][1] + cv + nfb[g * 256];
                float h3 = acc[1][nt][3] + cv + nfb[(g + 8) * 256];
                vs0 += siluf(h0) * w2;
                vs1 += siluf(h1) * w2;
                vs2 += siluf(h2) * w2;
                vs3 += siluf(h3) * w2;
            }
            #pragma unroll
            for (int off = 1; off <= 2; off <<= 1) {
                vs0 += __shfl_xor_sync(FULLMASK, vs0, off);
                vs1 += __shfl_xor_sync(FULLMASK, vs1, off);
                vs2 += __shfl_xor_sync(FULLMASK, vs2, off);
                vs3 += __shfl_xor_sync(FULLMASK, vs3, off);
            }
            if (tg == 0) {
                s_red[g * 8 + w]        = vs0;
                s_red[(g + 8) * 8 + w]  = vs1;
                s_red[(16 + g) * 8 + w] = vs2;
                s_red[(24 + g) * 8 + w] = vs3;
            }
            __syncthreads();
            if (t < 32) {
                float s = ts_b2[0];
                #pragma unroll
                for (int q = 0; q < 8; q++) s += s_red[t * 8 + q];
                s_logit[t] = s;
            }
            __syncthreads();
        }

        // ---- tw accumulators -> s_tw (aliases s_af; A reads done) ----
        #pragma unroll
        for (int nt = 0; nt < 8; nt++) {
            int tt = w * 32 + nt * 4 + tg;
            s_tw[g * 257 + tt]        = acc[0][nt][0];
            s_tw[(g + 8) * 257 + tt]  = acc[0][nt][2];
            s_tw[(16 + g) * 257 + tt] = acc[1][nt][0];
            s_tw[(24 + g) * 257 + tt] = acc[1][nt][2];
        }
        __syncthreads();

        // ---- Phase 4: softmax, t_attn, tmax, LN512 -> mix input columns ----
        {
            float tp_b2t = tp_b2[t];
            #pragma unroll
            for (int jj = 0; jj < 2; jj++) {
                int col = 2 * jg + jj;
                int j = j0 + col;
                float m = -1e30f;
                #pragma unroll
                for (int k = 0; k < 16; k++)
                    if (s_tk[k] != j) m = fmaxf(m, s_logit[jj * 16 + k]);
                float at[16];
                float den = 0.f;
                #pragma unroll
                for (int k = 0; k < 16; k++) {
                    at[k] = (s_tk[k] != j) ? __expf(s_logit[jj * 16 + k] - m) : 0.f;
                    den += at[k];
                }
                float inv = __frcp_rn(den);
                float ta = 0.f, tm = -1e30f;
                #pragma unroll
                for (int k = 0; k < 16; k++) {
                    float nf = node_s[((size_t)b * 64 + s_tk[k]) * 256 + t];
                    float tp = (s_tw[(jj * 16 + k) * 257 + t] + tp_b2t) * nf;
                    ta = fmaf(at[k] * inv, tp, ta);
                    if (s_tk[k] != j) tm = fmaxf(tm, tp);
                }
                float2 ss = block_reduce2(ta + tm, ta * ta + tm * tm, s_red);
                float mean = ss.x * (1.f / 512.f);
                float var  = ss.y * (1.f / 512.f) - mean * mean;
                float rs = rsqrtf(var + 1e-5f);
                s_mix16[t * 16 + col]         = (ta - mean) * rs * mix_ln_g[t]       + mix_ln_b[t];
                s_mix16[(256 + t) * 16 + col] = (tm - mean) * rs * mix_ln_g[256 + t] + mix_ln_b[256 + t];
            }
        }
        __syncthreads();   // protects s_tw/s_af, s_logit, s_red for next pass
    }

    // ==== Phases 5-7: batched over 16 edges, LDS.128 broadcast operands ====

    // ---- Phase 5: mix MLP ----
    u64 ctx2[8];
    {
        u64 h2[8];
        float bv = mix_b1[t];
        #pragma unroll
        for (int q = 0; q < 8; q++) PACK2(h2[q], bv, bv);
        #pragma unroll 8
        for (int e = 0; e < 512; e++) {
            float wv = mix_w1[e * 256 + t];
            u64 ww; PACK2(ww, wv, wv);
            const ulonglong2* xp = (const ulonglong2*)(s_mix16 + e * 16);
            ulonglong2 x0 = xp[0], x1 = xp[1], x2 = xp[2], x3 = xp[3];
            FMA2(h2[0], x0.x, ww, h2[0]);
            FMA2(h2[1], x0.y, ww, h2[1]);
            FMA2(h2[2], x1.x, ww, h2[2]);
            FMA2(h2[3], x1.y, ww, h2[3]);
            FMA2(h2[4], x2.x, ww, h2[4]);
            FMA2(h2[5], x2.y, ww, h2[5]);
            FMA2(h2[6], x3.x, ww, h2[6]);
            FMA2(h2[7], x3.y, ww, h2[7]);
        }
        float hv[16];
        #pragma unroll
        for (int q = 0; q < 8; q++) { UNPACK2(hv[2 * q], hv[2 * q + 1], h2[q]); }
        __syncthreads();   // s_af region (s_tw) fully read; safe to write s_hid16
        #pragma unroll
        for (int q = 0; q < 4; q++)
            ((float4*)(s_hid16 + t * 16))[q] =
                make_float4(siluf(hv[4 * q]), siluf(hv[4 * q + 1]),
                            siluf(hv[4 * q + 2]), siluf(hv[4 * q + 3]));
        __syncthreads();
        float cb = mix_b2[t];
        #pragma unroll
        for (int q = 0; q < 8; q++) PACK2(ctx2[q], cb, cb);
        #pragma unroll 8
        for (int e = 0; e < 256; e++) {
            float wv = mix_w2[e * 256 + t];
            u64 ww; PACK2(ww, wv, wv);
            const ulonglong2* xp = (const ulonglong2*)(s_hid16 + e * 16);
            ulonglong2 x0 = xp[0], x1 = xp[1], x2 = xp[2], x3 = xp[3];
            FMA2(ctx2[0], x0.x, ww, ctx2[0]);
            FMA2(ctx2[1], x0.y, ww, ctx2[1]);
            FMA2(ctx2[2], x1.x, ww, ctx2[2]);
            FMA2(ctx2[3], x1.y, ww, ctx2[3]);
            FMA2(ctx2[4], x2.x, ww, ctx2[4]);
            FMA2(ctx2[5], x2.y, ww, ctx2[5]);
            FMA2(ctx2[6], x3.x, ww, ctx2[6]);
            FMA2(ctx2[7], x3.y, ww, ctx2[7]);
        }
    }
    __syncthreads();   // all phase-5 reads of s_mix16 done (s_v16 alias safe later)

    // ---- Phase 6: edge MLP ----
    u64 base2[8];
    {
        u64 e2[8];
        float bv = ep_b1[t];
        #pragma unroll
        for (int q = 0; q < 8; q++) PACK2(e2[q], bv, bv);
        #pragma unroll 8
        for (int e = 0; e < 640; e++) {
            float wv = ep_w1[e * 256 + t];
            u64 ww; PACK2(ww, wv, wv);
            const ulonglong2* xp = (const ulonglong2*)(s_x16 + e * 16);
            ulonglong2 x0 = xp[0], x1 = xp[1], x2 = xp[2], x3 = xp[3];
            FMA2(e2[0], x0.x, ww, e2[0]);
            FMA2(e2[1], x0.y, ww, e2[1]);
            FMA2(e2[2], x1.x, ww, e2[2]);
            FMA2(e2[3], x1.y, ww, e2[3]);
            FMA2(e2[4], x2.x, ww, e2[4]);
            FMA2(e2[5], x2.y, ww, e2[5]);
            FMA2(e2[6], x3.x, ww, e2[6]);
            FMA2(e2[7], x3.y, ww, e2[7]);
        }
        float hv[16];
        #pragma unroll
        for (int q = 0; q < 8; q++) { UNPACK2(hv[2 * q], hv[2 * q + 1], e2[q]); }
        #pragma unroll
        for (int q = 0; q < 4; q++)
            ((float4*)(s_eh16 + t * 16))[q] =
                make_float4(siluf(hv[4 * q]), siluf(hv[4 * q + 1]),
                            siluf(hv[4 * q + 2]), siluf(hv[4 * q + 3]));
        __syncthreads();
        float bb = ep_b2[t];
        #pragma unroll
        for (int q = 0; q < 8; q++) PACK2(base2[q], bb, bb);
        #pragma unroll 8
        for (int e = 0; e < 256; e++) {
            float wv = ep_w2[e * 256 + t];
            u64 ww; PACK2(ww, wv, wv);
            const ulonglong2* xp = (const ulonglong2*)(s_eh16 + e * 16);
            ulonglong2 x0 = xp[0], x1 = xp[1], x2 = xp[2], x3 = xp[3];
            FMA2(base2[0], x0.x, ww, base2[0]);
            FMA2(base2[1], x0.y, ww, base2[1]);
            FMA2(base2[2], x1.x, ww, base2[2]);
            FMA2(base2[3], x1.y, ww, base2[3]);
            FMA2(base2[4], x2.x, ww, base2[4]);
            FMA2(base2[5], x2.y, ww, base2[5]);
            FMA2(base2[6], x3.x, ww, base2[6]);
            FMA2(base2[7], x3.y, ww, base2[7]);
        }
    }

    // ---- Phase 7: edge LN (per edge) -> s_v16, gate GEMM, store ----
    {
        float lng = edge_ln_g[t], lnb = edge_ln_b[t];
        #pragma unroll
        for (int q = 0; q < 8; q++) {
            float c0, c1, b0, b1v;
            UNPACK2(c0, c1, ctx2[q]);
            UNPACK2(b0, b1v, base2[q]);
            float ef0 = b0 + c0, ef1 = b1v + c1;
            float2 ss = block_reduce2(ef0, ef0 * ef0, s_red);
            float mean = ss.x * (1.f / 256.f);
            float var  = ss.y * (1.f / 256.f) - mean * mean;
            s_v16[t * 16 + 2 * q] = (ef0 - mean) * rsqrtf(var + 1e-5f) * lng + lnb;
            ss = block_reduce2(ef1, ef1 * ef1, s_red);
            mean = ss.x * (1.f / 256.f);
            var  = ss.y * (1.f / 256.f) - mean * mean;
            s_v16[t * 16 + 2 * q + 1] = (ef1 - mean) * rsqrtf(var + 1e-5f) * lng + lnb;
        }
    }
    __syncthreads();
    {
        u64 g2[8];
        float gb = gate_b[t];
        #pragma unroll
        for (int q = 0; q < 8; q++) PACK2(g2[q], gb, gb);
        #pragma unroll 8
        for (int e = 0; e < 256; e++) {
            float wv = gate_w[e * 256 + t];
            u64 ww; PACK2(ww, wv, wv);
            const ulonglong2* xp = (const ulonglong2*)(s_v16 + e * 16);
            ulonglong2 x0 = xp[0], x1 = xp[1], x2 = xp[2], x3 = xp[3];
            FMA2(g2[0], x0.x, ww, g2[0]);
            FMA2(g2[1], x0.y, ww, g2[1]);
            FMA2(g2[2], x1.x, ww, g2[2]);
            FMA2(g2[3], x1.y, ww, g2[3]);
            FMA2(g2[4], x2.x, ww, g2[4]);
            FMA2(g2[5], x2.y, ww, g2[5]);
            FMA2(g2[6], x3.x, ww, g2[6]);
            FMA2(g2[7], x3.y, ww, g2[7]);
        }
        float gv[16];
        #pragma unroll
        for (int q = 0; q < 8; q++) { UNPACK2(gv[2 * q], gv[2 * q + 1], g2[q]); }
        float vvv[16];
        #pragma unroll
        for (int q = 0; q < 4; q++) {
            float4 v4 = ((const float4*)(s_v16 + t * 16))[q];
            vvv[4 * q] = v4.x; vvv[4 * q + 1] = v4.y;
            vvv[4 * q + 2] = v4.z; vvv[4 * q + 3] = v4.w;
        }
        #pragma unroll
        for (int jj = 0; jj < 16; jj++)
            g_ef[((size_t)bi * 64 + j0 + jj) * 256 + t] = sigmf(gv[jj]) * vvv[jj];
    }
}

// ------------- node_delta: per (b,i) sum over j, LN, linear -----------------
__global__ __launch_bounds__(256) void node_kernel(
    const float* __restrict__ ln_g, const float* __restrict__ ln_b,
    const float* __restrict__ w, const float* __restrict__ bb,
    float* __restrict__ out) {
    __shared__ float s_v[256];
    __shared__ float s_red[20];
    int blk = blockIdx.x;   // b*64 + i
    int t = threadIdx.x;
    float s = 0.f;
    const float* base = g_ef + (size_t)blk * 64 * 256 + t;
    #pragma unroll 8
    for (int j = 0; j < 64; j++) s += base[j * 256];
    g_bondp[(size_t)blk * 256 + t] = s;
    float2 r2 = block_reduce2(s, s * s, s_red);
    float mean = r2.x * (1.f / 256.f);
    float var  = r2.y * (1.f / 256.f) - mean * mean;
    float v = (s - mean) * rsqrtf(var + 1e-5f) * ln_g[t] + ln_b[t];
    s_v[t] = v;
    __syncthreads();
    float o = bb[t];
    #pragma unroll 8
    for (int e = 0; e < 256; e++) o = fmaf(s_v[e], w[e * 256 + t], o);
    out[(size_t)blk * 256 + t] = o;
}

// ------------- bond_graph ----------------------------------------------------
__global__ void bond_kernel(float* __restrict__ out) {
    int b = blockIdx.x, t = threadIdx.x;
    float s = 0.f;
    #pragma unroll 8
    for (int i = 0; i < 64; i++) s += g_bondp[((size_t)b * 64 + i) * 256 + t];
    out[32768 + b * 256 + t] = s * (1.f / 4096.f);
}

// ---------------------------------------------------------------------------
extern "C" void kernel_launch(void* const* d_in, const int* in_sizes, int n_in,
                              void* d_out, int out_size) {
    const float* node_s    = (const float*)d_in[0];
    const float* dist      = (const float*)d_in[1];
    const float* rbf       = (const float*)d_in[2];
    const float* r_hat     = (const float*)d_in[3];
    const float* ep_w1     = (const float*)d_in[5];
    const float* ep_b1     = (const float*)d_in[6];
    const float* ep_w2     = (const float*)d_in[7];
    const float* ep_b2     = (const float*)d_in[8];
    const float* tp_w1     = (const float*)d_in[9];
    const float* tp_b1     = (const float*)d_in[10];
    const float* tp_w2     = (const float*)d_in[11];
    const float* tp_b2     = (const float*)d_in[12];
    const float* ts_w1     = (const float*)d_in[13];
    const float* ts_b1     = (const float*)d_in[14];
    const float* ts_w2     = (const float*)d_in[15];
    const float* ts_b2     = (const float*)d_in[16];
    const float* mix_ln_g  = (const float*)d_in[17];
    const float* mix_ln_b  = (const float*)d_in[18];
    const float* mix_w1    = (const float*)d_in[19];
    const float* mix_b1    = (const float*)d_in[20];
    const float* mix_w2    = (const float*)d_in[21];
    const float* mix_b2    = (const float*)d_in[22];
    const float* gate_w    = (const float*)d_in[23];
    const float* gate_b    = (const float*)d_in[24];
    const float* node_ln_g = (const float*)d_in[25];
    const float* node_ln_b = (const float*)d_in[26];
    const float* node_w    = (const float*)d_in[27];
    const float* node_b    = (const float*)d_in[28];
    const float* edge_ln_g = (const float*)d_in[29];
    const float* edge_ln_b = (const float*)d_in[30];
    float* out = (float*)d_out;

    cudaFuncSetAttribute(edge_kernel,
                         cudaFuncAttributeMaxDynamicSharedMemorySize, SM_TOTAL);

    prep_wc_kernel<<<257, 256>>>(tp_w2, ts_w1, tp_b2, ts_b1);
    topk_kernel<<<CB * CN, 32>>>(dist);
    pre_kernel<<<CB * CN * CK, 256>>>(node_s, rbf, tp_w1, tp_b1, ts_w1);
    edge_kernel<<<CB * CN * 4, 256, SM_TOTAL>>>(
        node_s, rbf, r_hat,
        tp_w1, tp_b2, ts_w2, ts_b2,
        ep_w1, ep_b1, ep_w2, ep_b2,
        mix_ln_g, mix_ln_b, mix_w1, mix_b1, mix_w2, mix_b2,
        gate_w, gate_b, edge_ln_g, edge_ln_b);
    node_kernel<<<CB * CN, 256>>>(node_ln_g, node_ln_b, node_w, node_b, out);
    bond_kernel<<<CB, 256>>>(out);
}

// round 15
// speedup vs baseline: 1.3175x; 1.3175x over previous
#include <cuda_runtime.h>
#include <math.h>

#define FULLMASK 0xffffffffu

typedef unsigned long long u64;
typedef unsigned int u32;

// Fixed problem sizes: B=2, N=64, D=256, R=128, K=16, H=256, ORD=3
constexpr int CB = 2, CN = 64, CK = 16;

// Dynamic smem layout (bytes), JB=16 edges per block
constexpr int SM_AF_BYTES  = 32896;                   // 8224 u32 (s_af / s_tw; post: frag stage)
constexpr int SM_X_OFF     = SM_AF_BYTES;             // 80*128 u32 = 40960 B (x fragments, K=640)
constexpr int SM_MIX_OFF   = SM_X_OFF + 40960;        // 64*128 u32 = 32768 B (mix fragments, K=512)
constexpr int SM_RED_OFF   = SM_MIX_OFF + 32768;      // 512 floats = 2048 B
constexpr int SM_LOGIT_OFF = SM_RED_OFF + 2048;       // 32 floats
constexpr int SM_CRH_OFF   = SM_LOGIT_OFF + 128;      // 48 floats
constexpr int SM_RH_OFF    = SM_CRH_OFF + 192;        // 48 floats
constexpr int SM_TK_OFF    = SM_RH_OFF + 192;         // 16 ints
constexpr int SM_TOTAL     = SM_TK_OFF + 64;          // 109248 B (x2 CTAs = 218496)

// ---------------- device scratch ----------------
// Fragment-ordered GEMM weights (phase 2): [kt:32][w:8][lane:32][half:2][nt:8] tf32.
__device__ u32 g_Wmma[32 * 8 * 32 * 16];
// Fragment-ordered MLP weights: [kstep][w:8][lane:32][half:2][nt:4] tf32.
__device__ u32 g_Wf_mix1[512 * 256];
__device__ u32 g_Wf_mix2[256 * 256];
__device__ u32 g_Wf_ep1[640 * 256];
__device__ u32 g_Wf_ep2[256 * 256];
__device__ u32 g_Wf_gate[256 * 256];
__device__ float g_cvec[256];                  // tp_b2 @ ts_w1a + ts_b1 (fp32)
__device__ int   g_topk[CB * CN * CK];
__device__ float g_radpre[CB * CN * CK * 256]; // comp_rbf @ tp_w1[4:] + tp_b1
__device__ float g_nfpre[CB * CN * CK * 256];  // comp_feat @ ts_w1[256:]
__device__ float g_ef[CB * CN * CN * 256];
__device__ float g_bondp[CB * CN * 256];

__device__ __forceinline__ float siluf(float x) { return x * __frcp_rn(1.f + __expf(-x)); }
__device__ __forceinline__ float sigmf(float x) { return __frcp_rn(1.f + __expf(-x)); }
__device__ __forceinline__ u32 f2tf(float x) {
    u32 r; asm("cvt.rna.tf32.f32 %0, %1;" : "=r"(r) : "f"(x)); return r;
}

__device__ __forceinline__ void mma_tf32(float* d, const u32* a, u32 b0, u32 b1) {
    asm volatile(
        "mma.sync.aligned.m16n8k8.row.col.f32.tf32.tf32.f32 "
        "{%0,%1,%2,%3}, {%4,%5,%6,%7}, {%8,%9}, {%0,%1,%2,%3};"
        : "+f"(d[0]), "+f"(d[1]), "+f"(d[2]), "+f"(d[3])
        : "r"(a[0]), "r"(a[1]), "r"(a[2]), "r"(a[3]), "r"(b0), "r"(b1));
}

// A-fragment slot for value (row m, k-dim d) in staged activation buffers.
__device__ __forceinline__ int aslot(int m, int d) {
    return (d >> 3) * 128 + ((m & 7) * 4 + (d & 3)) * 4 + (m >> 3) + 2 * ((d >> 2) & 1);
}

// MLP mma: C[16 x 256] += A[16 x 8K] @ W, warp w covers dims [w*32, w*32+32).
__device__ __forceinline__ void mlp_mma(float acc[4][4], const u32* __restrict__ Wf,
                                        const u32* s_actf, int ksteps,
                                        int wlane2, int lane4) {
    #pragma unroll
    for (int nt = 0; nt < 4; nt++) {
        acc[nt][0] = 0.f; acc[nt][1] = 0.f; acc[nt][2] = 0.f; acc[nt][3] = 0.f;
    }
    const uint4* wb = reinterpret_cast<const uint4*>(Wf) + wlane2;
    #pragma unroll 4
    for (int ks = 0; ks < ksteps; ks++) {
        uint4 a4 = *(const uint4*)(s_actf + ks * 128 + lane4);
        uint4 b0 = wb[ks * 512];
        uint4 b1 = wb[ks * 512 + 1];
        u32 a[4] = {a4.x, a4.y, a4.z, a4.w};
        mma_tf32(acc[0], a, b0.x, b1.x);
        mma_tf32(acc[1], a, b0.y, b1.y);
        mma_tf32(acc[2], a, b0.z, b1.z);
        mma_tf32(acc[3], a, b0.w, b1.w);
    }
}

// Stage C-fragment (plus bias, optional silu) into A-fragment layout (tf32 bits).
__device__ __forceinline__ void stage_c(u32* s_dst, const float acc[4][4],
                                        const float* __restrict__ bias,
                                        int w, int g, int tg, bool do_silu) {
    #pragma unroll
    for (int nt = 0; nt < 4; nt++) {
        int d0 = w * 32 + nt * 8 + 2 * tg;
        float bx = 0.f, by = 0.f;
        if (bias) { float2 bb = *(const float2*)(bias + d0); bx = bb.x; by = bb.y; }
        int ksbase = (w * 4 + nt) * 128;
        #pragma unroll
        for (int s = 0; s < 2; s++) {
            int dl = 2 * tg + s;
            int la = (g * 4 + (dl & 3)) * 4 + 2 * ((dl >> 2) & 1);
            float bv = s ? by : bx;
            float v0 = acc[nt][s] + bv;
            float v1 = acc[nt][2 + s] + bv;
            if (do_silu) { v0 = siluf(v0); v1 = siluf(v1); }
            s_dst[ksbase + la]     = f2tf(v0);
            s_dst[ksbase + la + 1] = f2tf(v1);
        }
    }
}

// Deterministic block-wide reduction of (sum, sumsq). scr >= 18 floats.
__device__ __forceinline__ float2 block_reduce2(float sx, float sy, float* scr) {
    #pragma unroll
    for (int off = 16; off; off >>= 1) {
        sx += __shfl_down_sync(FULLMASK, sx, off);
        sy += __shfl_down_sync(FULLMASK, sy, off);
    }
    int w = threadIdx.x >> 5;
    if ((threadIdx.x & 31) == 0) { scr[w] = sx; scr[8 + w] = sy; }
    __syncthreads();
    if (threadIdx.x == 0) {
        float ax = 0.f, ay = 0.f;
        #pragma unroll
        for (int q = 0; q < 8; q++) { ax += scr[q]; ay += scr[8 + q]; }
        scr[16] = ax; scr[17] = ay;
    }
    __syncthreads();
    float2 res = make_float2(scr[16], scr[17]);
    __syncthreads();
    return res;
}

// ------------- prep: fragment-ordered Wmma (tf32 bits), cvec -----------------
__global__ __launch_bounds__(256) void prep_wc_kernel(
    const float* __restrict__ tp_w2, const float* __restrict__ ts_w1,
    const float* __restrict__ tp_b2, const float* __restrict__ ts_b1) {
    __shared__ float row[256];
    int t = threadIdx.x;
    int d = blockIdx.x;
    if (d < 256) {
        float wv = tp_w2[d * 256 + t];
        row[t] = wv;
        __syncthreads();
        float acc = 0.f;
        #pragma unroll 4
        for (int e = 0; e < 256; e++) acc = fmaf(row[e], ts_w1[e * 256 + t], acc);
        int kt = d >> 3, r = d & 7, half = r >> 2, tg = r & 3;
        #pragma unroll
        for (int s = 0; s < 2; s++) {
            int n = 2 * t + s;
            int w = n >> 6, rem = n & 63, nt = rem >> 3, g = rem & 7;
            int lane = g * 4 + tg;
            g_Wmma[(((kt * 8 + w) * 32 + lane) << 4) + half * 8 + nt] =
                f2tf(s ? acc : wv);
        }
    } else {
        row[t] = tp_b2[t];
        __syncthreads();
        float acc = ts_b1[t];
        #pragma unroll 4
        for (int e = 0; e < 256; e++) acc = fmaf(row[e], ts_w1[e * 256 + t], acc);
        g_cvec[t] = acc;
    }
}

// ------------- prep: MLP weight fragments ------------------------------------
// src: [K][256] row-major. Element (e, t) -> b-frag slot.
__global__ __launch_bounds__(256) void prep_mlp_kernel(
    const float* __restrict__ src, u32* __restrict__ dst) {
    int e = blockIdx.x, t = threadIdx.x;
    float v = src[e * 256 + t];
    int kstep = e >> 3, tg = e & 3, half = (e >> 2) & 1;
    int w = t >> 5, nt = (t >> 3) & 3, g = t & 7;
    int idx = (((kstep * 8 + w) * 32 + g * 4 + tg) << 3) + half * 4 + nt;
    dst[idx] = f2tf(v);
}

// ------------- top-16 smallest dist per (b,i); ties -> lower index ----------
__global__ void topk_kernel(const float* __restrict__ dist) {
    int blk = blockIdx.x;           // b*64 + i
    int lane = threadIdx.x;
    const float* dr = dist + (size_t)blk * 64;
    float v0 = dr[lane], v1 = dr[lane + 32];
    for (int k = 0; k < 16; k++) {
        float bv = v0; int bj = lane;
        if (v1 < bv) { bv = v1; bj = lane + 32; }
        #pragma unroll
        for (int off = 16; off; off >>= 1) {
            float ov = __shfl_down_sync(FULLMASK, bv, off);
            int   oj = __shfl_down_sync(FULLMASK, bj, off);
            if (ov < bv || (ov == bv && oj < bj)) { bv = ov; bj = oj; }
        }
        int sel = __shfl_sync(FULLMASK, bj, 0);
        if (lane == 0) g_topk[blk * 16 + k] = sel;
        if (sel == lane)      v0 = INFINITY;
        if (sel == lane + 32) v1 = INFINITY;
    }
}

// ------------- per-(b,i,k) precompute: rad_pre, nf_pre ----------------------
__global__ __launch_bounds__(256) void pre_kernel(
    const float* __restrict__ node_s, const float* __restrict__ rbf,
    const float* __restrict__ tp_w1, const float* __restrict__ tp_b1,
    const float* __restrict__ ts_w1) {
    __shared__ float s_rbf[128];
    __shared__ float s_nd[256];
    int r = blockIdx.x;   // (b*64+i)*16 + k
    int t = threadIdx.x;
    int bi = r >> 4;
    int b = bi >> 6;
    int jk = g_topk[r];
    if (t < 128) s_rbf[t] = rbf[((size_t)bi * 64 + jk) * 128 + t];
    s_nd[t] = node_s[((size_t)b * 64 + jk) * 256 + t];
    __syncthreads();
    float rad = tp_b1[t];
    #pragma unroll 4
    for (int e = 0; e < 128; e++) rad = fmaf(s_rbf[e], tp_w1[(4 + e) * 256 + t], rad);
    float nf = 0.f;
    #pragma unroll 4
    for (int e = 0; e < 256; e++) nf = fmaf(s_nd[e], ts_w1[(256 + e) * 256 + t], nf);
    g_radpre[(size_t)r * 256 + t] = rad;
    g_nfpre[(size_t)r * 256 + t]  = nf;
}

// ------------- main fused edge kernel: 16 edges (j0..j0+15) per block -------
__global__ __launch_bounds__(256, 2) void edge_kernel(
    const float* __restrict__ node_s, const float* __restrict__ rbf,
    const float* __restrict__ r_hat,
    const float* __restrict__ tp_w1, const float* __restrict__ tp_b2,
    const float* __restrict__ ts_w2, const float* __restrict__ ts_b2,
    const float* __restrict__ ep_b1, const float* __restrict__ ep_b2,
    const float* __restrict__ mix_ln_g, const float* __restrict__ mix_ln_b,
    const float* __restrict__ mix_b1, const float* __restrict__ mix_b2,
    const float* __restrict__ gate_b,
    const float* __restrict__ edge_ln_g, const float* __restrict__ edge_ln_b) {

    extern __shared__ __align__(16) char smem_raw[];
    u32*   s_af    = (u32*)smem_raw;                    // [8224] loop: mma A frags
    float* s_tw    = (float*)smem_raw;                  // alias: [32][257]
    u32*   s_stage = (u32*)smem_raw;                    // alias post-loop: frag stage (16 KB)
    u32*   s_xf    = (u32*)(smem_raw + SM_X_OFF);       // [80*128] ep input frags
    u32*   s_mixf  = (u32*)(smem_raw + SM_MIX_OFF);     // [64*128] mix input frags
    float* s_red   = (float*)(smem_raw + SM_RED_OFF);   // [512]
    float* s_logit = (float*)(smem_raw + SM_LOGIT_OFF); // [32]
    float* s_crh   = (float*)(smem_raw + SM_CRH_OFF);   // [16*3]
    float* s_rh    = (float*)(smem_raw + SM_RH_OFF);    // [16*3]
    int*   s_tk    = (int*)(smem_raw + SM_TK_OFF);      // [16]

    int t = threadIdx.x;
    int lane = t & 31;
    int w = t >> 5;       // warp 0..7
    int g = lane >> 2;    // groupID 0..7
    int tg = lane & 3;    // threadInGroup 0..3
    int lane4 = lane * 4;
    int wlane2 = (w * 32 + lane) * 2;
    int bx = blockIdx.x;
    int b = bx >> 8;
    int rem = bx & 255;
    int i = rem >> 2;
    int j0 = (rem & 3) * 16;
    int bi = b * 64 + i;

    // ---- Phase 0: stage inputs; ep-MLP inputs written in fragment order ----
    {
        float nsit = node_s[(size_t)bi * 256 + t];
        u32 nv = f2tf(nsit);
        #pragma unroll
        for (int m = 0; m < 16; m++) s_xf[aslot(m, t)] = nv;
        #pragma unroll
        for (int m = 0; m < 16; m++)
            s_xf[aslot(m, 256 + t)] = f2tf(node_s[((size_t)b * 64 + j0 + m) * 256 + t]);
        if (t < 128) {
            #pragma unroll
            for (int m = 0; m < 16; m++)
                s_xf[aslot(m, 512 + t)] = f2tf(rbf[((size_t)bi * 64 + j0 + m) * 128 + t]);
        }
        if (t < 16) s_tk[t] = g_topk[bi * 16 + t];
        if (t < 48) s_crh[t] = r_hat[((size_t)bi * 64 + g_topk[bi * 16 + t / 3]) * 3 + (t % 3)];
        if (t < 48) s_rh[t] = r_hat[((size_t)bi * 64 + j0 + t / 3) * 3 + (t % 3)];
    }
    __syncthreads();

    // ==== jg loop: 8 passes x 2 edges through phases 1-4 ====
    for (int jg = 0; jg < 8; jg++) {
        // ---- Phase 1: a = silu(layer1), scattered into fragment order ----
        {
            float w1_0 = tp_w1[t], w1_1 = tp_w1[256 + t], w1_2 = tp_w1[512 + t], w1_3 = tp_w1[768 + t];
            int ekt = t >> 3, etg = t & 3, ehi = (t >> 2) & 1;
            int ej0 = 2 * jg;
            float rx0 = s_rh[ej0 * 3], ry0 = s_rh[ej0 * 3 + 1], rz0 = s_rh[ej0 * 3 + 2];
            float rx1 = s_rh[ej0 * 3 + 3], ry1 = s_rh[ej0 * 3 + 4], rz1 = s_rh[ej0 * 3 + 5];
            #pragma unroll
            for (int k = 0; k < 16; k++) {
                float rad = g_radpre[((size_t)bi * 16 + k) * 256 + t] + w1_0;
                float cx = s_crh[k * 3], cy = s_crh[k * 3 + 1], cz = s_crh[k * 3 + 2];
                int gw = k & 7;
                int lw = gw * 4 + etg;
                int q = ((k >> 3) & 1) + 2 * ehi;
                #pragma unroll
                for (int jj = 0; jj < 2; jj++) {
                    float c = jj ? (rx1 * cx + ry1 * cy + rz1 * cz)
                                 : (rx0 * cx + ry0 * cy + rz0 * cz);
                    c = fminf(fmaxf(c, -1.f + 1e-6f), 1.f - 1e-6f);
                    float p1 = c;
                    float p2 = (3.f * c * p1 - 1.f) * 0.5f;
                    float p3 = (5.f * c * p2 - 2.f * p1) * (1.f / 3.f);
                    float h = rad;
                    h = fmaf(p1, w1_1, h);
                    h = fmaf(p2, w1_2, h);
                    h = fmaf(p3, w1_3, h);
                    s_af[ekt * 256 + lw * 8 + ((jj * 4) ^ (lw & 4)) + q] = f2tf(siluf(h));
                }
            }
        }
        __syncthreads();

        // ---- Phase 2: tensor-core GEMM C[32x512] = A[32x256] @ W[256x512] ----
        float acc[2][8][4];
        #pragma unroll
        for (int mt = 0; mt < 2; mt++)
            #pragma unroll
            for (int nt = 0; nt < 8; nt++)
                #pragma unroll
                for (int q = 0; q < 4; q++) acc[mt][nt][q] = 0.f;
        {
            int sw = lane & 4;
            const uint4* wbase = reinterpret_cast<const uint4*>(g_Wmma) + ((w * 32 + lane) << 2);
            #pragma unroll 2
            for (int kt = 0; kt < 32; kt++) {
                const uint4* wr = wbase + (kt << 10);
                uint4 B0 = wr[0];
                uint4 B1 = wr[1];
                uint4 B2 = wr[2];
                uint4 B3 = wr[3];
                const u32* ab = s_af + kt * 256 + lane * 8;
                uint4 A0 = *(const uint4*)(ab + sw);
                uint4 A1 = *(const uint4*)(ab + (4 ^ sw));
                u32 a0[4] = {A0.x, A0.y, A0.z, A0.w};
                u32 a1[4] = {A1.x, A1.y, A1.z, A1.w};
                mma_tf32(acc[0][0], a0, B0.x, B2.x);
                mma_tf32(acc[1][0], a1, B0.x, B2.x);
                mma_tf32(acc[0][1], a0, B0.y, B2.y);
                mma_tf32(acc[1][1], a1, B0.y, B2.y);
                mma_tf32(acc[0][2], a0, B0.z, B2.z);
                mma_tf32(acc[1][2], a1, B0.z, B2.z);
                mma_tf32(acc[0][3], a0, B0.w, B2.w);
                mma_tf32(acc[1][3], a1, B0.w, B2.w);
                mma_tf32(acc[0][4], a0, B1.x, B3.x);
                mma_tf32(acc[1][4], a1, B1.x, B3.x);
                mma_tf32(acc[0][5], a0, B1.y, B3.y);
                mma_tf32(acc[1][5], a1, B1.y, B3.y);
                mma_tf32(acc[0][6], a0, B1.z, B3.z);
                mma_tf32(acc[1][6], a1, B1.z, B3.z);
                mma_tf32(acc[0][7], a0, B1.w, B3.w);
                mma_tf32(acc[1][7], a1, B1.w, B3.w);
            }
        }

        // ---- Phase 3: logits from ts accumulators ----
        {
            float vs0 = 0.f, vs1 = 0.f, vs2 = 0.f, vs3 = 0.f;
            #pragma unroll
            for (int nt = 0; nt < 8; nt++) {
                int tt = w * 32 + nt * 4 + tg;
                float cv = g_cvec[tt];
                float w2 = ts_w2[tt];
                const float* nfb = g_nfpre + (size_t)bi * 4096 + tt;
                float h0 = acc[0][nt][1] + cv + nfb[g * 256];
                float h1 = acc[0][nt][3] + cv + nfb[(g + 8) * 256];
                float h2 = acc[1][nt][1] + cv + nfb[g * 256];
                float h3 = acc[1][nt][3] + cv + nfb[(g + 8) * 256];
                vs0 += siluf(h0) * w2;
                vs1 += siluf(h1) * w2;
                vs2 += siluf(h2) * w2;
                vs3 += siluf(h3) * w2;
            }
            #pragma unroll
            for (int off = 1; off <= 2; off <<= 1) {
                vs0 += __shfl_xor_sync(FULLMASK, vs0, off);
                vs1 += __shfl_xor_sync(FULLMASK, vs1, off);
                vs2 += __shfl_xor_sync(FULLMASK, vs2, off);
                vs3 += __shfl_xor_sync(FULLMASK, vs3, off);
            }
            if (tg == 0) {
                s_red[g * 8 + w]        = vs0;
                s_red[(g + 8) * 8 + w]  = vs1;
                s_red[(16 + g) * 8 + w] = vs2;
                s_red[(24 + g) * 8 + w] = vs3;
            }
            __syncthreads();
            if (t < 32) {
                float s = ts_b2[0];
                #pragma unroll
                for (int q = 0; q < 8; q++) s += s_red[t * 8 + q];
                s_logit[t] = s;
            }
            __syncthreads();
        }

        // ---- tw accumulators -> s_tw (aliases s_af; A reads done) ----
        #pragma unroll
        for (int nt = 0; nt < 8; nt++) {
            int tt = w * 32 + nt * 4 + tg;
            s_tw[g * 257 + tt]        = acc[0][nt][0];
            s_tw[(g + 8) * 257 + tt]  = acc[0][nt][2];
            s_tw[(16 + g) * 257 + tt] = acc[1][nt][0];
            s_tw[(24 + g) * 257 + tt] = acc[1][nt][2];
        }
        __syncthreads();

        // ---- Phase 4: softmax, t_attn, tmax, LN512 -> mix frag columns ----
        {
            float tp_b2t = tp_b2[t];
            #pragma unroll
            for (int jj = 0; jj < 2; jj++) {
                int col = 2 * jg + jj;
                int j = j0 + col;
                float m = -1e30f;
                #pragma unroll
                for (int k = 0; k < 16; k++)
                    if (s_tk[k] != j) m = fmaxf(m, s_logit[jj * 16 + k]);
                float at[16];
                float den = 0.f;
                #pragma unroll
                for (int k = 0; k < 16; k++) {
                    at[k] = (s_tk[k] != j) ? __expf(s_logit[jj * 16 + k] - m) : 0.f;
                    den += at[k];
                }
                float inv = __frcp_rn(den);
                float ta = 0.f, tm = -1e30f;
                #pragma unroll
                for (int k = 0; k < 16; k++) {
                    float nf = node_s[((size_t)b * 64 + s_tk[k]) * 256 + t];
                    float tp = (s_tw[(jj * 16 + k) * 257 + t] + tp_b2t) * nf;
                    ta = fmaf(at[k] * inv, tp, ta);
                    if (s_tk[k] != j) tm = fmaxf(tm, tp);
                }
                float2 ss = block_reduce2(ta + tm, ta * ta + tm * tm, s_red);
                float mean = ss.x * (1.f / 512.f);
                float var  = ss.y * (1.f / 512.f) - mean * mean;
                float rs = rsqrtf(var + 1e-5f);
                float v1 = (ta - mean) * rs * mix_ln_g[t]       + mix_ln_b[t];
                float v2 = (tm - mean) * rs * mix_ln_g[256 + t] + mix_ln_b[256 + t];
                s_mixf[aslot(col, t)]       = f2tf(v1);
                s_mixf[aslot(col, 256 + t)] = f2tf(v2);
            }
        }
        __syncthreads();   // protects s_tw/s_af, s_logit, s_red for next pass
    }

    // ==== Phases 5-7: all MLP layers on tensor cores (M=16 edges) ====
    float accA[4][4], accB[4][4];

    // ---- mix layer 1 (K=512) -> silu -> stage (s_stage aliases s_af) ----
    mlp_mma(accA, g_Wf_mix1, s_mixf, 64, wlane2, lane4);
    stage_c(s_stage, accA, mix_b1, w, g, tg, true);
    __syncthreads();

    // ---- mix layer 2 (K=256) -> ctx (+mix_b2) in accB ----
    mlp_mma(accB, g_Wf_mix2, s_stage, 32, wlane2, lane4);
    #pragma unroll
    for (int nt = 0; nt < 4; nt++) {
        float2 bb = *(const float2*)(mix_b2 + w * 32 + nt * 8 + 2 * tg);
        accB[nt][0] += bb.x; accB[nt][1] += bb.y;
        accB[nt][2] += bb.x; accB[nt][3] += bb.y;
    }
    __syncthreads();   // all mix2 reads of s_stage done before ep1 restages

    // ---- ep layer 1 (K=640) -> silu -> stage ----
    mlp_mma(accA, g_Wf_ep1, s_xf, 80, wlane2, lane4);
    stage_c(s_stage, accA, ep_b1, w, g, tg, true);
    __syncthreads();

    // ---- ep layer 2 (K=256) -> ef = ep2 + ep_b2 + ctx (into accA) ----
    mlp_mma(accA, g_Wf_ep2, s_stage, 32, wlane2, lane4);
    #pragma unroll
    for (int nt = 0; nt < 4; nt++) {
        float2 bb = *(const float2*)(ep_b2 + w * 32 + nt * 8 + 2 * tg);
        accA[nt][0] += bb.x + accB[nt][0];
        accA[nt][1] += bb.y + accB[nt][1];
        accA[nt][2] += bb.x + accB[nt][2];
        accA[nt][3] += bb.y + accB[nt][3];
    }

    // ---- batched per-edge LN over 256 dims ----
    {
        float pg = 0.f, pg2 = 0.f, ph = 0.f, ph2 = 0.f;
        #pragma unroll
        for (int nt = 0; nt < 4; nt++) {
            pg  += accA[nt][0] + accA[nt][1];
            pg2 += accA[nt][0] * accA[nt][0] + accA[nt][1] * accA[nt][1];
            ph  += accA[nt][2] + accA[nt][3];
            ph2 += accA[nt][2] * accA[nt][2] + accA[nt][3] * accA[nt][3];
        }
        #pragma unroll
        for (int off = 1; off <= 2; off <<= 1) {
            pg  += __shfl_xor_sync(FULLMASK, pg, off);
            pg2 += __shfl_xor_sync(FULLMASK, pg2, off);
            ph  += __shfl_xor_sync(FULLMASK, ph, off);
            ph2 += __shfl_xor_sync(FULLMASK, ph2, off);
        }
        if (tg == 0) {
            s_red[g * 8 + w]             = pg;
            s_red[256 + g * 8 + w]       = pg2;
            s_red[(g + 8) * 8 + w]       = ph;
            s_red[256 + (g + 8) * 8 + w] = ph2;
        }
        __syncthreads();
        if (t < 16) {
            float s = 0.f, s2 = 0.f;
            #pragma unroll
            for (int q = 0; q < 8; q++) { s += s_red[t * 8 + q]; s2 += s_red[256 + t * 8 + q]; }
            float mean = s * (1.f / 256.f);
            float var  = s2 * (1.f / 256.f) - mean * mean;
            s_logit[t]      = mean;
            s_logit[16 + t] = rsqrtf(var + 1e-5f);
        }
        __syncthreads();
    }

    // ---- v = LN(ef) into accB; stage v fragments for gate ----
    {
        float mg = s_logit[g],     rg = s_logit[16 + g];
        float mh = s_logit[g + 8], rh = s_logit[16 + g + 8];
        #pragma unroll
        for (int nt = 0; nt < 4; nt++) {
            int d0 = w * 32 + nt * 8 + 2 * tg;
            float2 lg = *(const float2*)(edge_ln_g + d0);
            float2 lb = *(const float2*)(edge_ln_b + d0);
            accB[nt][0] = (accA[nt][0] - mg) * rg * lg.x + lb.x;
            accB[nt][1] = (accA[nt][1] - mg) * rg * lg.y + lb.y;
            accB[nt][2] = (accA[nt][2] - mh) * rh * lg.x + lb.x;
            accB[nt][3] = (accA[nt][3] - mh) * rh * lg.y + lb.y;
        }
    }
    stage_c(s_stage, accB, (const float*)0, w, g, tg, false);
    __syncthreads();

    // ---- gate (K=256) -> sigmoid * v -> store ----
    mlp_mma(accA, g_Wf_gate, s_stage, 32, wlane2, lane4);
    {
        size_t rowg = ((size_t)bi * 64 + j0 + g) * 256;
        size_t rowh = ((size_t)bi * 64 + j0 + g + 8) * 256;
        #pragma unroll
        for (int nt = 0; nt < 4; nt++) {
            int d0 = w * 32 + nt * 8 + 2 * tg;
            float2 gb = *(const float2*)(gate_b + d0);
            float2 og = make_float2(sigmf(accA[nt][0] + gb.x) * accB[nt][0],
                                    sigmf(accA[nt][1] + gb.y) * accB[nt][1]);
            float2 oh = make_float2(sigmf(accA[nt][2] + gb.x) * accB[nt][2],
                                    sigmf(accA[nt][3] + gb.y) * accB[nt][3]);
            *(float2*)(g_ef + rowg + d0) = og;
            *(float2*)(g_ef + rowh + d0) = oh;
        }
    }
}

// ------------- node_delta: per (b,i) sum over j, LN, linear -----------------
__global__ __launch_bounds__(256) void node_kernel(
    const float* __restrict__ ln_g, const float* __restrict__ ln_b,
    const float* __restrict__ w, const float* __restrict__ bb,
    float* __restrict__ out) {
    __shared__ float s_v[256];
    __shared__ float s_red[20];
    int blk = blockIdx.x;   // b*64 + i
    int t = threadIdx.x;
    float s = 0.f;
    const float* base = g_ef + (size_t)blk * 64 * 256 + t;
    #pragma unroll 8
    for (int j = 0; j < 64; j++) s += base[j * 256];
    g_bondp[(size_t)blk * 256 + t] = s;
    float2 r2 = block_reduce2(s, s * s, s_red);
    float mean = r2.x * (1.f / 256.f);
    float var  = r2.y * (1.f / 256.f) - mean * mean;
    float v = (s - mean) * rsqrtf(var + 1e-5f) * ln_g[t] + ln_b[t];
    s_v[t] = v;
    __syncthreads();
    float o = bb[t];
    #pragma unroll 8
    for (int e = 0; e < 256; e++) o = fmaf(s_v[e], w[e * 256 + t], o);
    out[(size_t)blk * 256 + t] = o;
}

// ------------- bond_graph ----------------------------------------------------
__global__ void bond_kernel(float* __restrict__ out) {
    int b = blockIdx.x, t = threadIdx.x;
    float s = 0.f;
    #pragma unroll 8
    for (int i = 0; i < 64; i++) s += g_bondp[((size_t)b * 64 + i) * 256 + t];
    out[32768 + b * 256 + t] = s * (1.f / 4096.f);
}

// ---------------------------------------------------------------------------
extern "C" void kernel_launch(void* const* d_in, const int* in_sizes, int n_in,
                              void* d_out, int out_size) {
    const float* node_s    = (const float*)d_in[0];
    const float* dist      = (const float*)d_in[1];
    const float* rbf       = (const float*)d_in[2];
    const float* r_hat     = (const float*)d_in[3];
    const float* ep_w1     = (const float*)d_in[5];
    const float* ep_b1     = (const float*)d_in[6];
    const float* ep_w2     = (const float*)d_in[7];
    const float* ep_b2     = (const float*)d_in[8];
    const float* tp_w1     = (const float*)d_in[9];
    const float* tp_b1     = (const float*)d_in[10];
    const float* tp_w2     = (const float*)d_in[11];
    const float* tp_b2     = (const float*)d_in[12];
    const float* ts_w1     = (const float*)d_in[13];
    const float* ts_b1     = (const float*)d_in[14];
    const float* ts_w2     = (const float*)d_in[15];
    const float* ts_b2     = (const float*)d_in[16];
    const float* mix_ln_g  = (const float*)d_in[17];
    const float* mix_ln_b  = (const float*)d_in[18];
    const float* mix_w1    = (const float*)d_in[19];
    const float* mix_b1    = (const float*)d_in[20];
    const float* mix_w2    = (const float*)d_in[21];
    const float* mix_b2    = (const float*)d_in[22];
    const float* gate_w    = (const float*)d_in[23];
    const float* gate_b    = (const float*)d_in[24];
    const float* node_ln_g = (const float*)d_in[25];
    const float* node_ln_b = (const float*)d_in[26];
    const float* node_w    = (const float*)d_in[27];
    const float* node_b    = (const float*)d_in[28];
    const float* edge_ln_g = (const float*)d_in[29];
    const float* edge_ln_b = (const float*)d_in[30];
    float* out = (float*)d_out;

    u32 *d_mix1, *d_mix2, *d_ep1, *d_ep2, *d_gate;
    cudaGetSymbolAddress((void**)&d_mix1, g_Wf_mix1);
    cudaGetSymbolAddress((void**)&d_mix2, g_Wf_mix2);
    cudaGetSymbolAddress((void**)&d_ep1,  g_Wf_ep1);
    cudaGetSymbolAddress((void**)&d_ep2,  g_Wf_ep2);
    cudaGetSymbolAddress((void**)&d_gate, g_Wf_gate);

    cudaFuncSetAttribute(edge_kernel,
                         cudaFuncAttributeMaxDynamicSharedMemorySize, SM_TOTAL);

    prep_wc_kernel<<<257, 256>>>(tp_w2, ts_w1, tp_b2, ts_b1);
    prep_mlp_kernel<<<512, 256>>>(mix_w1, d_mix1);
    prep_mlp_kernel<<<256, 256>>>(mix_w2, d_mix2);
    prep_mlp_kernel<<<640, 256>>>(ep_w1, d_ep1);
    prep_mlp_kernel<<<256, 256>>>(ep_w2, d_ep2);
    prep_mlp_kernel<<<256, 256>>>(gate_w, d_gate);
    topk_kernel<<<CB * CN, 32>>>(dist);
    pre_kernel<<<CB * CN * CK, 256>>>(node_s, rbf, tp_w1, tp_b1, ts_w1);
    edge_kernel<<<CB * CN * 4, 256, SM_TOTAL>>>(
        node_s, rbf, r_hat,
        tp_w1, tp_b2, ts_w2, ts_b2,
        ep_b1, ep_b2,
        mix_ln_g, mix_ln_b, mix_b1, mix_b2,
        gate_b, edge_ln_g, edge_ln_b);
    node_kernel<<<CB * CN, 256>>>(node_ln_g, node_ln_b, node_w, node_b, out);
    bond_kernel<<<CB, 256>>>(out);
}

// round 17
// speedup vs baseline: 1.6513x; 1.2534x over previous
#include <cuda_runtime.h>
#include <math.h>

#define FULLMASK 0xffffffffu

typedef unsigned long long u64;
typedef unsigned int u32;

// Fixed problem sizes: B=2, N=64, D=256, R=128, K=16, H=256, ORD=3
constexpr int CB = 2, CN = 64, CK = 16;

// Dynamic smem layout (bytes), JB=16 edges per block
// Region A (0..66048): jg-loop: s_af (64KB) then s_tw (64x258 f = 66048B);
//                      post-loop: s_xf (40960B) + s_stage (16384B).
constexpr int SM_A_BYTES   = 66048;
constexpr int SM_MIXF_OFF  = SM_A_BYTES;              // 64*128 u32 = 32768 B
constexpr int SM_RED_OFF   = SM_MIXF_OFF + 32768;     // 512 floats = 2048 B
constexpr int SM_LOGIT_OFF = SM_RED_OFF + 2048;       // 64 floats = 256 B
constexpr int SM_CRH_OFF   = SM_LOGIT_OFF + 256;      // 48 floats
constexpr int SM_RH_OFF    = SM_CRH_OFF + 192;        // 48 floats
constexpr int SM_TK_OFF    = SM_RH_OFF + 192;         // 16 ints
constexpr int SM_TOTAL     = SM_TK_OFF + 64;          // 101568 B

// ---------------- device scratch ----------------
// Phase-2 weights, fragment order: [kt:32][w:8][lane:32][half:2][nt:4] tf32.
__device__ u32 g_Wtw[32 * 8 * 32 * 8];
__device__ u32 g_Wts[32 * 8 * 32 * 8];
// MLP weights, fragment order: [kstep][w:8][lane:32][half:2][nt:4] tf32.
__device__ u32 g_Wf_mix1[512 * 256];
__device__ u32 g_Wf_mix2[256 * 256];
__device__ u32 g_Wf_ep1[640 * 256];
__device__ u32 g_Wf_ep2[256 * 256];
__device__ u32 g_Wf_gate[256 * 256];
__device__ float g_cvec[256];
__device__ int   g_topk[CB * CN * CK];
__device__ float g_radpre[CB * CN * CK * 256];
__device__ float g_nfpre[CB * CN * CK * 256];
__device__ float g_ef[CB * CN * CN * 256];
__device__ float g_bondp[CB * CN * 256];

__device__ __forceinline__ float siluf(float x) { return x * __frcp_rn(1.f + __expf(-x)); }
__device__ __forceinline__ float sigmf(float x) { return __frcp_rn(1.f + __expf(-x)); }
__device__ __forceinline__ u32 f2tf(float x) {
    u32 r; asm("cvt.rna.tf32.f32 %0, %1;" : "=r"(r) : "f"(x)); return r;
}

__device__ __forceinline__ void mma_tf32(float* d, const u32* a, u32 b0, u32 b1) {
    asm volatile(
        "mma.sync.aligned.m16n8k8.row.col.f32.tf32.tf32.f32 "
        "{%0,%1,%2,%3}, {%4,%5,%6,%7}, {%8,%9}, {%0,%1,%2,%3};"
        : "+f"(d[0]), "+f"(d[1]), "+f"(d[2]), "+f"(d[3])
        : "r"(a[0]), "r"(a[1]), "r"(a[2]), "r"(a[3]), "r"(b0), "r"(b1));
}

// A-fragment slot for (row m, k-dim d) in M=16 staged MLP buffers.
__device__ __forceinline__ int aslot(int m, int d) {
    return (d >> 3) * 128 + ((m & 7) * 4 + (d & 3)) * 4 + (m >> 3) + 2 * ((d >> 2) & 1);
}

// MLP mma: C[16 x 256] += A[16 x 8K] @ W, warp w covers dims [w*32, w*32+32).
__device__ __forceinline__ void mlp_mma(float acc[4][4], const u32* __restrict__ Wf,
                                        const u32* s_actf, int ksteps,
                                        int wlane2, int lane4) {
    #pragma unroll
    for (int nt = 0; nt < 4; nt++) {
        acc[nt][0] = 0.f; acc[nt][1] = 0.f; acc[nt][2] = 0.f; acc[nt][3] = 0.f;
    }
    const uint4* wb = reinterpret_cast<const uint4*>(Wf) + wlane2;
    #pragma unroll 4
    for (int ks = 0; ks < ksteps; ks++) {
        uint4 a4 = *(const uint4*)(s_actf + ks * 128 + lane4);
        uint4 b0 = wb[ks * 512];
        uint4 b1 = wb[ks * 512 + 1];
        u32 a[4] = {a4.x, a4.y, a4.z, a4.w};
        mma_tf32(acc[0], a, b0.x, b1.x);
        mma_tf32(acc[1], a, b0.y, b1.y);
        mma_tf32(acc[2], a, b0.z, b1.z);
        mma_tf32(acc[3], a, b0.w, b1.w);
    }
}

// Stage C-fragment (plus bias, optional silu) into A-fragment layout (tf32).
__device__ __forceinline__ void stage_c(u32* s_dst, const float acc[4][4],
                                        const float* __restrict__ bias,
                                        int w, int g, int tg, bool do_silu) {
    #pragma unroll
    for (int nt = 0; nt < 4; nt++) {
        int d0 = w * 32 + nt * 8 + 2 * tg;
        float bx = 0.f, by = 0.f;
        if (bias) { float2 bb = *(const float2*)(bias + d0); bx = bb.x; by = bb.y; }
        int ksbase = (w * 4 + nt) * 128;
        #pragma unroll
        for (int s = 0; s < 2; s++) {
            int dl = 2 * tg + s;
            int la = (g * 4 + (dl & 3)) * 4 + 2 * ((dl >> 2) & 1);
            float bv = s ? by : bx;
            float v0 = acc[nt][s] + bv;
            float v1 = acc[nt][2 + s] + bv;
            if (do_silu) { v0 = siluf(v0); v1 = siluf(v1); }
            s_dst[ksbase + la]     = f2tf(v0);
            s_dst[ksbase + la + 1] = f2tf(v1);
        }
    }
}

// Deterministic block-wide reduction of (sum, sumsq). scr >= 18 floats.
__device__ __forceinline__ float2 block_reduce2(float sx, float sy, float* scr) {
    #pragma unroll
    for (int off = 16; off; off >>= 1) {
        sx += __shfl_down_sync(FULLMASK, sx, off);
        sy += __shfl_down_sync(FULLMASK, sy, off);
    }
    int w = threadIdx.x >> 5;
    if ((threadIdx.x & 31) == 0) { scr[w] = sx; scr[8 + w] = sy; }
    __syncthreads();
    if (threadIdx.x == 0) {
        float ax = 0.f, ay = 0.f;
        #pragma unroll
        for (int q = 0; q < 8; q++) { ax += scr[q]; ay += scr[8 + q]; }
        scr[16] = ax; scr[17] = ay;
    }
    __syncthreads();
    float2 res = make_float2(scr[16], scr[17]);
    __syncthreads();
    return res;
}

// ------------- prep: phase-2 weight fragments (N=256 map), cvec --------------
__global__ __launch_bounds__(256) void prep_wc_kernel(
    const float* __restrict__ tp_w2, const float* __restrict__ ts_w1,
    const float* __restrict__ tp_b2, const float* __restrict__ ts_b1) {
    __shared__ float row[256];
    int t = threadIdx.x;
    int d = blockIdx.x;
    if (d < 256) {
        float wv = tp_w2[d * 256 + t];
        row[t] = wv;
        __syncthreads();
        float acc = 0.f;
        #pragma unroll 4
        for (int e = 0; e < 256; e++) acc = fmaf(row[e], ts_w1[e * 256 + t], acc);
        // e = d (K dim), n = t (output dim)
        int kt = d >> 3, er = d & 7, half = er >> 2, er3 = er & 3;
        int wn = t >> 5, ntw = (t >> 3) & 3, lanew = (t & 7) * 4 + er3;
        int idx = (((kt * 8 + wn) * 32 + lanew) << 3) + half * 4 + ntw;
        g_Wtw[idx] = f2tf(wv);
        g_Wts[idx] = f2tf(acc);
    } else {
        row[t] = tp_b2[t];
        __syncthreads();
        float acc = ts_b1[t];
        #pragma unroll 4
        for (int e = 0; e < 256; e++) acc = fmaf(row[e], ts_w1[e * 256 + t], acc);
        g_cvec[t] = acc;
    }
}

// ------------- prep: MLP weight fragments (two batched launches) -------------
__device__ __forceinline__ void mlp_frag_store(const float* src, u32* dst, int e, int t) {
    float v = src[e * 256 + t];
    int kstep = e >> 3, tg = e & 3, half = (e >> 2) & 1;
    int w = t >> 5, nt = (t >> 3) & 3, g = t & 7;
    dst[(((kstep * 8 + w) * 32 + g * 4 + tg) << 3) + half * 4 + nt] = f2tf(v);
}
__global__ __launch_bounds__(256) void prep_mlpA_kernel(
    const float* __restrict__ mix_w1, u32* dst_mix1,
    const float* __restrict__ ep_w1, u32* dst_ep1) {
    int e = blockIdx.x, t = threadIdx.x;
    if (e < 512) mlp_frag_store(mix_w1, dst_mix1, e, t);
    else         mlp_frag_store(ep_w1, dst_ep1, e - 512, t);
}
__global__ __launch_bounds__(256) void prep_mlpB_kernel(
    const float* __restrict__ mix_w2, u32* dst_mix2,
    const float* __restrict__ ep_w2, u32* dst_ep2,
    const float* __restrict__ gate_w, u32* dst_gate) {
    int e = blockIdx.x, t = threadIdx.x;
    if (e < 256)      mlp_frag_store(mix_w2, dst_mix2, e, t);
    else if (e < 512) mlp_frag_store(ep_w2, dst_ep2, e - 256, t);
    else              mlp_frag_store(gate_w, dst_gate, e - 512, t);
}

// ------------- top-16 smallest dist per (b,i); ties -> lower index ----------
__global__ void topk_kernel(const float* __restrict__ dist) {
    int blk = blockIdx.x;
    int lane = threadIdx.x;
    const float* dr = dist + (size_t)blk * 64;
    float v0 = dr[lane], v1 = dr[lane + 32];
    for (int k = 0; k < 16; k++) {
        float bv = v0; int bj = lane;
        if (v1 < bv) { bv = v1; bj = lane + 32; }
        #pragma unroll
        for (int off = 16; off; off >>= 1) {
            float ov = __shfl_down_sync(FULLMASK, bv, off);
            int   oj = __shfl_down_sync(FULLMASK, bj, off);
            if (ov < bv || (ov == bv && oj < bj)) { bv = ov; bj = oj; }
        }
        int sel = __shfl_sync(FULLMASK, bj, 0);
        if (lane == 0) g_topk[blk * 16 + k] = sel;
        if (sel == lane)      v0 = INFINITY;
        if (sel == lane + 32) v1 = INFINITY;
    }
}

// ------------- per-(b,i,k) precompute: rad_pre, nf_pre ----------------------
__global__ __launch_bounds__(256) void pre_kernel(
    const float* __restrict__ node_s, const float* __restrict__ rbf,
    const float* __restrict__ tp_w1, const float* __restrict__ tp_b1,
    const float* __restrict__ ts_w1) {
    __shared__ float s_rbf[128];
    __shared__ float s_nd[256];
    int r = blockIdx.x;
    int t = threadIdx.x;
    int bi = r >> 4;
    int b = bi >> 6;
    int jk = g_topk[r];
    if (t < 128) s_rbf[t] = rbf[((size_t)bi * 64 + jk) * 128 + t];
    s_nd[t] = node_s[((size_t)b * 64 + jk) * 256 + t];
    __syncthreads();
    float rad = tp_b1[t];
    #pragma unroll 4
    for (int e = 0; e < 128; e++) rad = fmaf(s_rbf[e], tp_w1[(4 + e) * 256 + t], rad);
    float nf = 0.f;
    #pragma unroll 4
    for (int e = 0; e < 256; e++) nf = fmaf(s_nd[e], ts_w1[(256 + e) * 256 + t], nf);
    g_radpre[(size_t)r * 256 + t] = rad;
    g_nfpre[(size_t)r * 256 + t]  = nf;
}

// ------------- main fused edge kernel: 16 edges per block -------------------
__global__ __launch_bounds__(256, 2) void edge_kernel(
    const float* __restrict__ node_s, const float* __restrict__ rbf,
    const float* __restrict__ r_hat,
    const float* __restrict__ tp_w1, const float* __restrict__ tp_b2,
    const float* __restrict__ ts_w2, const float* __restrict__ ts_b2,
    const float* __restrict__ ep_b1, const float* __restrict__ ep_b2,
    const float* __restrict__ mix_ln_g, const float* __restrict__ mix_ln_b,
    const float* __restrict__ mix_b1, const float* __restrict__ mix_b2,
    const float* __restrict__ gate_b,
    const float* __restrict__ edge_ln_g, const float* __restrict__ edge_ln_b) {

    extern __shared__ __align__(16) char smem_raw[];
    u32*   s_af    = (u32*)smem_raw;                    // loop: M=64 A frags (64KB)
    float* s_tw    = (float*)smem_raw;                  // alias: [64][258]
    u32*   s_xf    = (u32*)smem_raw;                    // post-loop: [80*128]
    u32*   s_stage = (u32*)smem_raw + 10240;            // post-loop: [32*128]
    u32*   s_mixf  = (u32*)(smem_raw + SM_MIXF_OFF);    // [64*128]
    float* s_red   = (float*)(smem_raw + SM_RED_OFF);   // [512]
    float* s_logit = (float*)(smem_raw + SM_LOGIT_OFF); // [64]
    float* s_crh   = (float*)(smem_raw + SM_CRH_OFF);   // [16*3]
    float* s_rh    = (float*)(smem_raw + SM_RH_OFF);    // [16*3]
    int*   s_tk    = (int*)(smem_raw + SM_TK_OFF);      // [16]

    int t = threadIdx.x;
    int lane = t & 31;
    int w = t >> 5;
    int g = lane >> 2;
    int tg = lane & 3;
    int lane4 = lane * 4;
    int wlane2 = (w * 32 + lane) * 2;
    int bx = blockIdx.x;
    int b = bx >> 8;
    int rem = bx & 255;
    int i = rem >> 2;
    int j0 = (rem & 3) * 16;
    int bi = b * 64 + i;

    // ---- Phase 0: tiny staging ----
    if (t < 16) s_tk[t] = g_topk[bi * 16 + t];
    if (t < 48) s_crh[t] = r_hat[((size_t)bi * 64 + g_topk[bi * 16 + t / 3]) * 3 + (t % 3)];
    if (t < 48) s_rh[t] = r_hat[((size_t)bi * 64 + j0 + t / 3) * 3 + (t % 3)];
    __syncthreads();

    // nf cache: node_s[topk[k]][t], invariant across passes
    float nfreg[16];
    #pragma unroll
    for (int k = 0; k < 16; k++)
        nfreg[k] = node_s[((size_t)b * 64 + s_tk[k]) * 256 + t];

    // ==== jg loop: 4 passes x 4 edges ====
    for (int jg = 0; jg < 4; jg++) {
        // ---- Phase 1: A[row=jj*16+k][e=t] = silu(layer1), fragment order ----
        {
            float w1_0 = tp_w1[t], w1_1 = tp_w1[256 + t], w1_2 = tp_w1[512 + t], w1_3 = tp_w1[768 + t];
            int ekt = t >> 3, etg = t & 3, ehi = (t >> 2) & 1;
            float rv[12];
            #pragma unroll
            for (int jj = 0; jj < 4; jj++) {
                int ej = 4 * jg + jj;
                rv[jj * 3]     = s_rh[ej * 3];
                rv[jj * 3 + 1] = s_rh[ej * 3 + 1];
                rv[jj * 3 + 2] = s_rh[ej * 3 + 2];
            }
            #pragma unroll
            for (int k = 0; k < 16; k++) {
                float rad = g_radpre[((size_t)bi * 16 + k) * 256 + t] + w1_0;
                float cx = s_crh[k * 3], cy = s_crh[k * 3 + 1], cz = s_crh[k * 3 + 2];
                int lanew = (k & 7) * 4 + etg;
                int q = (k >> 3) + 2 * ehi;
                #pragma unroll
                for (int jj = 0; jj < 4; jj++) {
                    float c = rv[jj * 3] * cx + rv[jj * 3 + 1] * cy + rv[jj * 3 + 2] * cz;
                    c = fminf(fmaxf(c, -1.f + 1e-6f), 1.f - 1e-6f);
                    float p1 = c;
                    float p2 = (3.f * c * p1 - 1.f) * 0.5f;
                    float p3 = (5.f * c * p2 - 2.f * p1) * (1.f / 3.f);
                    float h = rad;
                    h = fmaf(p1, w1_1, h);
                    h = fmaf(p2, w1_2, h);
                    h = fmaf(p3, w1_3, h);
                    s_af[((ekt * 4 + jj) * 32 + lanew) * 4 + q] = f2tf(siluf(h));
                }
            }
        }
        __syncthreads();

        float acc[4][4][4];

        // ---- Phase 2a: ts-GEMM C[64x256] = A @ Wts ----
        #pragma unroll
        for (int mt = 0; mt < 4; mt++)
            #pragma unroll
            for (int nt = 0; nt < 4; nt++)
                #pragma unroll
                for (int q = 0; q < 4; q++) acc[mt][nt][q] = 0.f;
        {
            const uint4* wb = reinterpret_cast<const uint4*>(g_Wts) + wlane2;
            const uint4* af4 = reinterpret_cast<const uint4*>(s_af);
            #pragma unroll 2
            for (int kt = 0; kt < 32; kt++) {
                uint4 B0 = wb[kt * 512];
                uint4 B1 = wb[kt * 512 + 1];
                uint4 A[4];
                #pragma unroll
                for (int mt = 0; mt < 4; mt++) A[mt] = af4[(kt * 4 + mt) * 32 + lane];
                #pragma unroll
                for (int mt = 0; mt < 4; mt++) {
                    u32 a[4] = {A[mt].x, A[mt].y, A[mt].z, A[mt].w};
                    mma_tf32(acc[mt][0], a, B0.x, B1.x);
                    mma_tf32(acc[mt][1], a, B0.y, B1.y);
                    mma_tf32(acc[mt][2], a, B0.z, B1.z);
                    mma_tf32(acc[mt][3], a, B0.w, B1.w);
                }
            }
        }

        // ---- Phase 3: logits (reduce over n) ----
        {
            #pragma unroll
            for (int mt = 0; mt < 4; mt++) {
                float p0 = 0.f, p1 = 0.f;
                #pragma unroll
                for (int nt = 0; nt < 4; nt++) {
                    int n0 = w * 32 + nt * 8 + 2 * tg;
                    float2 cv = *(const float2*)(g_cvec + n0);
                    float2 w2 = *(const float2*)(ts_w2 + n0);
                    const float* nfb = g_nfpre + (size_t)bi * 4096 + n0;
                    float2 nfg = *(const float2*)(nfb + g * 256);
                    float2 nfh = *(const float2*)(nfb + (g + 8) * 256);
                    p0 += siluf(acc[mt][nt][0] + cv.x + nfg.x) * w2.x
                        + siluf(acc[mt][nt][1] + cv.y + nfg.y) * w2.y;
                    p1 += siluf(acc[mt][nt][2] + cv.x + nfh.x) * w2.x
                        + siluf(acc[mt][nt][3] + cv.y + nfh.y) * w2.y;
                }
                p0 += __shfl_xor_sync(FULLMASK, p0, 1);
                p0 += __shfl_xor_sync(FULLMASK, p0, 2);
                p1 += __shfl_xor_sync(FULLMASK, p1, 1);
                p1 += __shfl_xor_sync(FULLMASK, p1, 2);
                if (tg == 0) {
                    s_red[(mt * 16 + g) * 8 + w]     = p0;
                    s_red[(mt * 16 + g + 8) * 8 + w] = p1;
                }
            }
            __syncthreads();
            if (t < 64) {
                float s = ts_b2[0];
                #pragma unroll
                for (int q = 0; q < 8; q++) s += s_red[t * 8 + q];
                s_logit[t] = s;
            }
        }

        // ---- Phase 2b: tw-GEMM (A re-read) ----
        #pragma unroll
        for (int mt = 0; mt < 4; mt++)
            #pragma unroll
            for (int nt = 0; nt < 4; nt++)
                #pragma unroll
                for (int q = 0; q < 4; q++) acc[mt][nt][q] = 0.f;
        {
            const uint4* wb = reinterpret_cast<const uint4*>(g_Wtw) + wlane2;
            const uint4* af4 = reinterpret_cast<const uint4*>(s_af);
            #pragma unroll 2
            for (int kt = 0; kt < 32; kt++) {
                uint4 B0 = wb[kt * 512];
                uint4 B1 = wb[kt * 512 + 1];
                uint4 A[4];
                #pragma unroll
                for (int mt = 0; mt < 4; mt++) A[mt] = af4[(kt * 4 + mt) * 32 + lane];
                #pragma unroll
                for (int mt = 0; mt < 4; mt++) {
                    u32 a[4] = {A[mt].x, A[mt].y, A[mt].z, A[mt].w};
                    mma_tf32(acc[mt][0], a, B0.x, B1.x);
                    mma_tf32(acc[mt][1], a, B0.y, B1.y);
                    mma_tf32(acc[mt][2], a, B0.z, B1.z);
                    mma_tf32(acc[mt][3], a, B0.w, B1.w);
                }
            }
        }
        __syncthreads();   // all A reads done before s_tw overwrites region A

        // tw -> s_tw transpose
        #pragma unroll
        for (int mt = 0; mt < 4; mt++)
            #pragma unroll
            for (int nt = 0; nt < 4; nt++) {
                int n0 = w * 32 + nt * 8 + 2 * tg;
                *(float2*)(s_tw + (mt * 16 + g) * 258 + n0) =
                    make_float2(acc[mt][nt][0], acc[mt][nt][1]);
                *(float2*)(s_tw + (mt * 16 + g + 8) * 258 + n0) =
                    make_float2(acc[mt][nt][2], acc[mt][nt][3]);
            }
        __syncthreads();

        // ---- Phase 4: softmax, t_attn, tmax, batched LN512 -> mix frags ----
        {
            float tp_b2t = tp_b2[t];
            float tav[4], tmv[4], sxv[4], syv[4];
            #pragma unroll
            for (int jj = 0; jj < 4; jj++) {
                int col = 4 * jg + jj;
                int j = j0 + col;
                float m = -1e30f;
                #pragma unroll
                for (int k = 0; k < 16; k++)
                    if (s_tk[k] != j) m = fmaxf(m, s_logit[jj * 16 + k]);
                float at[16];
                float den = 0.f;
                #pragma unroll
                for (int k = 0; k < 16; k++) {
                    at[k] = (s_tk[k] != j) ? __expf(s_logit[jj * 16 + k] - m) : 0.f;
                    den += at[k];
                }
                float inv = __frcp_rn(den);
                float ta = 0.f, tm = -1e30f;
                #pragma unroll
                for (int k = 0; k < 16; k++) {
                    float tp = (s_tw[(jj * 16 + k) * 258 + t] + tp_b2t) * nfreg[k];
                    ta = fmaf(at[k] * inv, tp, ta);
                    if (s_tk[k] != j) tm = fmaxf(tm, tp);
                }
                tav[jj] = ta; tmv[jj] = tm;
                sxv[jj] = ta + tm;
                syv[jj] = ta * ta + tm * tm;
            }
            #pragma unroll
            for (int jj = 0; jj < 4; jj++)
                #pragma unroll
                for (int off = 16; off; off >>= 1) {
                    sxv[jj] += __shfl_down_sync(FULLMASK, sxv[jj], off);
                    syv[jj] += __shfl_down_sync(FULLMASK, syv[jj], off);
                }
            if (lane == 0) {
                #pragma unroll
                for (int jj = 0; jj < 4; jj++) {
                    s_red[jj * 8 + w]      = sxv[jj];
                    s_red[32 + jj * 8 + w] = syv[jj];
                }
            }
            __syncthreads();
            if (t < 4) {
                float s = 0.f, s2 = 0.f;
                #pragma unroll
                for (int q = 0; q < 8; q++) { s += s_red[t * 8 + q]; s2 += s_red[32 + t * 8 + q]; }
                float mean = s * (1.f / 512.f);
                float var  = s2 * (1.f / 512.f) - mean * mean;
                s_red[64 + t] = mean;
                s_red[68 + t] = rsqrtf(var + 1e-5f);
            }
            __syncthreads();
            float lg1 = mix_ln_g[t], lb1 = mix_ln_b[t];
            float lg2 = mix_ln_g[256 + t], lb2 = mix_ln_b[256 + t];
            #pragma unroll
            for (int jj = 0; jj < 4; jj++) {
                float mean = s_red[64 + jj], rs = s_red[68 + jj];
                int col = 4 * jg + jj;
                s_mixf[aslot(col, t)]       = f2tf((tav[jj] - mean) * rs * lg1 + lb1);
                s_mixf[aslot(col, 256 + t)] = f2tf((tmv[jj] - mean) * rs * lg2 + lb2);
            }
        }
        __syncthreads();   // region A (s_tw) reads done before next ph1 / s_xf
    }

    // ---- stage ep-MLP inputs into s_xf (region A now free) ----
    {
        float nsit = node_s[(size_t)bi * 256 + t];
        u32 nv = f2tf(nsit);
        #pragma unroll
        for (int m = 0; m < 16; m++) s_xf[aslot(m, t)] = nv;
        #pragma unroll
        for (int m = 0; m < 16; m++)
            s_xf[aslot(m, 256 + t)] = f2tf(node_s[((size_t)b * 64 + j0 + m) * 256 + t]);
        if (t < 128) {
            #pragma unroll
            for (int m = 0; m < 16; m++)
                s_xf[aslot(m, 512 + t)] = f2tf(rbf[((size_t)bi * 64 + j0 + m) * 128 + t]);
        }
    }

    // ==== MLP layers on tensor cores (M=16 edges) ====
    float accA[4][4], accB[4][4];

    // mix layer 1 (K=512) -> silu -> stage
    mlp_mma(accA, g_Wf_mix1, s_mixf, 64, wlane2, lane4);
    stage_c(s_stage, accA, mix_b1, w, g, tg, true);
    __syncthreads();   // orders s_xf writes + s_stage writes block-wide

    // mix layer 2 (K=256) -> ctx (+mix_b2)
    mlp_mma(accB, g_Wf_mix2, s_stage, 32, wlane2, lane4);
    #pragma unroll
    for (int nt = 0; nt < 4; nt++) {
        float2 bb = *(const float2*)(mix_b2 + w * 32 + nt * 8 + 2 * tg);
        accB[nt][0] += bb.x; accB[nt][1] += bb.y;
        accB[nt][2] += bb.x; accB[nt][3] += bb.y;
    }
    __syncthreads();

    // ep layer 1 (K=640) -> silu -> stage
    mlp_mma(accA, g_Wf_ep1, s_xf, 80, wlane2, lane4);
    stage_c(s_stage, accA, ep_b1, w, g, tg, true);
    __syncthreads();

    // ep layer 2 (K=256) -> ef = ep2 + ep_b2 + ctx
    mlp_mma(accA, g_Wf_ep2, s_stage, 32, wlane2, lane4);
    #pragma unroll
    for (int nt = 0; nt < 4; nt++) {
        float2 bb = *(const float2*)(ep_b2 + w * 32 + nt * 8 + 2 * tg);
        accA[nt][0] += bb.x + accB[nt][0];
        accA[nt][1] += bb.y + accB[nt][1];
        accA[nt][2] += bb.x + accB[nt][2];
        accA[nt][3] += bb.y + accB[nt][3];
    }

    // batched per-edge LN over 256 dims
    {
        float pg = 0.f, pg2 = 0.f, ph = 0.f, ph2 = 0.f;
        #pragma unroll
        for (int nt = 0; nt < 4; nt++) {
            pg  += accA[nt][0] + accA[nt][1];
            pg2 += accA[nt][0] * accA[nt][0] + accA[nt][1] * accA[nt][1];
            ph  += accA[nt][2] + accA[nt][3];
            ph2 += accA[nt][2] * accA[nt][2] + accA[nt][3] * accA[nt][3];
        }
        #pragma unroll
        for (int off = 1; off <= 2; off <<= 1) {
            pg  += __shfl_xor_sync(FULLMASK, pg, off);
            pg2 += __shfl_xor_sync(FULLMASK, pg2, off);
            ph  += __shfl_xor_sync(FULLMASK, ph, off);
            ph2 += __shfl_xor_sync(FULLMASK, ph2, off);
        }
        if (tg == 0) {
            s_red[g * 8 + w]             = pg;
            s_red[256 + g * 8 + w]       = pg2;
            s_red[(g + 8) * 8 + w]       = ph;
            s_red[256 + (g + 8) * 8 + w] = ph2;
        }
        __syncthreads();
        if (t < 16) {
            float s = 0.f, s2 = 0.f;
            #pragma unroll
            for (int q = 0; q < 8; q++) { s += s_red[t * 8 + q]; s2 += s_red[256 + t * 8 + q]; }
            float mean = s * (1.f / 256.f);
            float var  = s2 * (1.f / 256.f) - mean * mean;
            s_logit[t]      = mean;
            s_logit[16 + t] = rsqrtf(var + 1e-5f);
        }
        __syncthreads();
    }

    // v = LN(ef); stage v fragments for gate
    {
        float mg = s_logit[g],     rg = s_logit[16 + g];
        float mh = s_logit[g + 8], rh = s_logit[16 + g + 8];
        #pragma unroll
        for (int nt = 0; nt < 4; nt++) {
            int d0 = w * 32 + nt * 8 + 2 * tg;
            float2 lg = *(const float2*)(edge_ln_g + d0);
            float2 lb = *(const float2*)(edge_ln_b + d0);
            accB[nt][0] = (accA[nt][0] - mg) * rg * lg.x + lb.x;
            accB[nt][1] = (accA[nt][1] - mg) * rg * lg.y + lb.y;
            accB[nt][2] = (accA[nt][2] - mh) * rh * lg.x + lb.x;
            accB[nt][3] = (accA[nt][3] - mh) * rh * lg.y + lb.y;
        }
    }
    stage_c(s_stage, accB, (const float*)0, w, g, tg, false);
    __syncthreads();

    // gate (K=256) -> sigmoid * v -> store
    mlp_mma(accA, g_Wf_gate, s_stage, 32, wlane2, lane4);
    {
        size_t rowg = ((size_t)bi * 64 + j0 + g) * 256;
        size_t rowh = ((size_t)bi * 64 + j0 + g + 8) * 256;
        #pragma unroll
        for (int nt = 0; nt < 4; nt++) {
            int d0 = w * 32 + nt * 8 + 2 * tg;
            float2 gb = *(const float2*)(gate_b + d0);
            float2 og = make_float2(sigmf(accA[nt][0] + gb.x) * accB[nt][0],
                                    sigmf(accA[nt][1] + gb.y) * accB[nt][1]);
            float2 oh = make_float2(sigmf(accA[nt][2] + gb.x) * accB[nt][2],
                                    sigmf(accA[nt][3] + gb.y) * accB[nt][3]);
            *(float2*)(g_ef + rowg + d0) = og;
            *(float2*)(g_ef + rowh + d0) = oh;
        }
    }
}

// ------------- node_delta ----------------------------------------------------
__global__ __launch_bounds__(256) void node_kernel(
    const float* __restrict__ ln_g, const float* __restrict__ ln_b,
    const float* __restrict__ w, const float* __restrict__ bb,
    float* __restrict__ out) {
    __shared__ float s_v[256];
    __shared__ float s_red[20];
    int blk = blockIdx.x;
    int t = threadIdx.x;
    float s = 0.f;
    const float* base = g_ef + (size_t)blk * 64 * 256 + t;
    #pragma unroll 8
    for (int j = 0; j < 64; j++) s += base[j * 256];
    g_bondp[(size_t)blk * 256 + t] = s;
    float2 r2 = block_reduce2(s, s * s, s_red);
    float mean = r2.x * (1.f / 256.f);
    float var  = r2.y * (1.f / 256.f) - mean * mean;
    float v = (s - mean) * rsqrtf(var + 1e-5f) * ln_g[t] + ln_b[t];
    s_v[t] = v;
    __syncthreads();
    float o = bb[t];
    #pragma unroll 8
    for (int e = 0; e < 256; e++) o = fmaf(s_v[e], w[e * 256 + t], o);
    out[(size_t)blk * 256 + t] = o;
}

// ------------- bond_graph ----------------------------------------------------
__global__ void bond_kernel(float* __restrict__ out) {
    int b = blockIdx.x, t = threadIdx.x;
    float s = 0.f;
    #pragma unroll 8
    for (int i = 0; i < 64; i++) s += g_bondp[((size_t)b * 64 + i) * 256 + t];
    out[32768 + b * 256 + t] = s * (1.f / 4096.f);
}

// ---------------------------------------------------------------------------
extern "C" void kernel_launch(void* const* d_in, const int* in_sizes, int n_in,
                              void* d_out, int out_size) {
    const float* node_s    = (const float*)d_in[0];
    const float* dist      = (const float*)d_in[1];
    const float* rbf       = (const float*)d_in[2];
    const float* r_hat     = (const float*)d_in[3];
    const float* ep_w1     = (const float*)d_in[5];
    const float* ep_b1     = (const float*)d_in[6];
    const float* ep_w2     = (const float*)d_in[7];
    const float* ep_b2     = (const float*)d_in[8];
    const float* tp_w1     = (const float*)d_in[9];
    const float* tp_b1     = (const float*)d_in[10];
    const float* tp_w2     = (const float*)d_in[11];
    const float* tp_b2     = (const float*)d_in[12];
    const float* ts_w1     = (const float*)d_in[13];
    const float* ts_b1     = (const float*)d_in[14];
    const float* ts_w2     = (const float*)d_in[15];
    const float* ts_b2     = (const float*)d_in[16];
    const float* mix_ln_g  = (const float*)d_in[17];
    const float* mix_ln_b  = (const float*)d_in[18];
    const float* mix_w1    = (const float*)d_in[19];
    const float* mix_b1    = (const float*)d_in[20];
    const float* mix_w2    = (const float*)d_in[21];
    const float* mix_b2    = (const float*)d_in[22];
    const float* gate_w    = (const float*)d_in[23];
    const float* gate_b    = (const float*)d_in[24];
    const float* node_ln_g = (const float*)d_in[25];
    const float* node_ln_b = (const float*)d_in[26];
    const float* node_w    = (const float*)d_in[27];
    const float* node_b    = (const float*)d_in[28];
    const float* edge_ln_g = (const float*)d_in[29];
    const float* edge_ln_b = (const float*)d_in[30];
    float* out = (float*)d_out;

    u32 *d_mix1, *d_mix2, *d_ep1, *d_ep2, *d_gate;
    cudaGetSymbolAddress((void**)&d_mix1, g_Wf_mix1);
    cudaGetSymbolAddress((void**)&d_mix2, g_Wf_mix2);
    cudaGetSymbolAddress((void**)&d_ep1,  g_Wf_ep1);
    cudaGetSymbolAddress((void**)&d_ep2,  g_Wf_ep2);
    cudaGetSymbolAddress((void**)&d_gate, g_Wf_gate);

    cudaFuncSetAttribute(edge_kernel,
                         cudaFuncAttributeMaxDynamicSharedMemorySize, SM_TOTAL);

    prep_wc_kernel<<<257, 256>>>(tp_w2, ts_w1, tp_b2, ts_b1);
    prep_mlpA_kernel<<<1152, 256>>>(mix_w1, d_mix1, ep_w1, d_ep1);
    prep_mlpB_kernel<<<768, 256>>>(mix_w2, d_mix2, ep_w2, d_ep2, gate_w, d_gate);
    topk_kernel<<<CB * CN, 32>>>(dist);
    pre_kernel<<<CB * CN * CK, 256>>>(node_s, rbf, tp_w1, tp_b1, ts_w1);
    edge_kernel<<<CB * CN * 4, 256, SM_TOTAL>>>(
        node_s, rbf, r_hat,
        tp_w1, tp_b2, ts_w2, ts_b2,
        ep_b1, ep_b2,
        mix_ln_g, mix_ln_b, mix_b1, mix_b2,
        gate_b, edge_ln_g, edge_ln_b);
    node_kernel<<<CB * CN, 256>>>(node_ln_g, node_ln_b, node_w, node_b, out);
    bond_kernel<<<CB, 256>>>(out);
}